// round 9
// baseline (speedup 1.0000x reference)
#include <cuda_runtime.h>
#include <cuda_fp16.h>
#include <cstdint>

#define Bn 256
#define Qn 16
#define Sn 512
#define Mn 8
#define Dn 128
#define NT 256
#define TILE 64
#define NCHUNK 8
#define PPITCH 520
#define CGP 132

typedef unsigned long long ull;

// ---- shared memory layout (float offsets) ----
#define OFF_QT   0          // qT[128][16]
#define OFF_P    2048       // p[16][520]
#define OFF_W    10368      // w[512]
#define OFF_OUT  10880      // out [q][128]
#define OFF_KBAR 12928      // kbar [q][128]
#define OFF_OCG  14976      // cg out [q][128]
#define OFF_KBCG 17024      // cg kbar [q][128]
#define OFF_KCG  19072      // kcg[8][132]
#define OFF_VCG  20128      // vcg[8][132]
#define OFF_PCG  21184      // p_cg[16][8]
#define OFF_WCG  21312      // w_cg[8]
#define OFF_RED  21320      // 8 warps * 4
#define OFF_K32  21376      // fp32 stage K [64][129] -> 29632
#define OFF_V32  29632      // fp32 stage V [64][129] -> 37888
// fp16 tiles [128 d][64 s] = 4096 floats each, 128B rows, swizzled
#define OFF_VH   37888
#define OFF_VL   41984
#define OFF_WKH  46080
#define OFF_KH   50176
#define OFF_PH   54272      // p fp16 [16 q][64 s] = 512 floats
#define OFF_PL   54784
#define SMEM_FLOATS 55296   // 221184 bytes

__device__ float g_losses[Bn];

__device__ __forceinline__ float clip50(float x) {
    return fminf(fmaxf(x, -50.0f), 50.0f);
}
__device__ __forceinline__ ull dup2(float x) {
    ull r; asm("mov.b64 %0, {%1, %1};" : "=l"(r) : "f"(x)); return r;
}
__device__ __forceinline__ ull fma2(ull a, ull b, ull c) {
    ull d; asm("fma.rn.f32x2 %0, %1, %2, %3;" : "=l"(d) : "l"(a), "l"(b), "l"(c)); return d;
}
__device__ __forceinline__ float2 unpack2(ull p) {
    float2 f; asm("mov.b64 {%0, %1}, %2;" : "=f"(f.x), "=f"(f.y) : "l"(p)); return f;
}
__device__ __forceinline__ uint32_t smem_u32(const void* p) {
    uint32_t a;
    asm("{ .reg .u64 t; cvta.to.shared.u64 t, %1; cvt.u32.u64 %0, t; }" : "=r"(a) : "l"(p));
    return a;
}
__device__ __forceinline__ void split2h(float f0, float f1, uint32_t& hi, uint32_t& lo) {
    __half2 h = __floats2half2_rn(f0, f1);
    float2 hf = __half22float2(h);
    __half2 l = __floats2half2_rn(f0 - hf.x, f1 - hf.y);
    hi = *(uint32_t*)&h;
    lo = *(uint32_t*)&l;
}
__device__ __forceinline__ uint32_t cvt2h(float f0, float f1) {
    __half2 h = __floats2half2_rn(f0, f1);
    return *(uint32_t*)&h;
}
__device__ __forceinline__ uint32_t swz(uint32_t off) { return off ^ ((off >> 3) & 0x70); }

__device__ __forceinline__ void ldsm4(uint32_t& r0, uint32_t& r1, uint32_t& r2, uint32_t& r3, uint32_t a) {
    asm volatile("ldmatrix.sync.aligned.m8n8.x4.shared.b16 {%0,%1,%2,%3}, [%4];"
                 : "=r"(r0), "=r"(r1), "=r"(r2), "=r"(r3) : "r"(a));
}
__device__ __forceinline__ void mma16816(float* d, const uint32_t* a, uint32_t b0, uint32_t b1) {
    asm volatile("mma.sync.aligned.m16n8k16.row.col.f32.f16.f16.f32 "
                 "{%0,%1,%2,%3}, {%4,%5,%6,%7}, {%8,%9}, {%0,%1,%2,%3};"
                 : "+f"(d[0]), "+f"(d[1]), "+f"(d[2]), "+f"(d[3])
                 : "r"(a[0]), "r"(a[1]), "r"(a[2]), "r"(a[3]), "r"(b0), "r"(b1));
}

__global__ void __launch_bounds__(NT, 1)
fml_kernel(const float* __restrict__ gq, const float* __restrict__ gk,
           const float* __restrict__ gv, const float* __restrict__ gkcg,
           const float* __restrict__ gvcg)
{
    extern __shared__ float sm[];
    char* smc = (char*)sm;
    const int b   = blockIdx.x;
    const int tid = threadIdx.x;
    const int wid = tid >> 5, lane = tid & 31;
    const float scale = 0.088388347648318447f;
    const uint32_t smb = smem_u32(sm);

    // ---- load qT [d][16] and cg tensors ----
    const float* qb = gq + (size_t)b * Qn * Dn;
    for (int i = tid; i < Qn * Dn; i += NT) {
        int qq = i >> 7, d = i & 127;
        sm[OFF_QT + d * 16 + qq] = qb[i];
    }
    const float* kcb = gkcg + (size_t)b * Mn * Dn;
    const float* vcb = gvcg + (size_t)b * Mn * Dn;
    for (int i = tid; i < Mn * Dn; i += NT) {
        int j = i >> 7, d = i & 127;
        sm[OFF_KCG + j * CGP + d] = kcb[i];
        sm[OFF_VCG + j * CGP + d] = vcb[i];
    }
    __syncthreads();

    // ---- cg scores / softmax / w_cg / out / kbar (exact SIMT) ----
    if (tid < Qn * Mn) {
        int qq = tid >> 3, j = tid & 7;
        float acc = 0.f;
        #pragma unroll 8
        for (int d = 0; d < Dn; ++d)
            acc = fmaf(sm[OFF_QT + d * 16 + qq], sm[OFF_KCG + j * CGP + d], acc);
        sm[OFF_PCG + qq * Mn + j] = acc * scale;
    }
    __syncthreads();
    if (tid < Qn) {
        float m = -1e30f;
        #pragma unroll
        for (int j = 0; j < Mn; ++j) m = fmaxf(m, sm[OFF_PCG + tid * Mn + j]);
        float ss = 0.f;
        #pragma unroll
        for (int j = 0; j < Mn; ++j) {
            float e = __expf(sm[OFF_PCG + tid * Mn + j] - m);
            sm[OFF_PCG + tid * Mn + j] = e; ss += e;
        }
        float inv = 1.f / ss;
        #pragma unroll
        for (int j = 0; j < Mn; ++j) sm[OFF_PCG + tid * Mn + j] *= inv;
    }
    __syncthreads();
    if (tid < Mn) {
        float a = 0.f;
        #pragma unroll
        for (int qq = 0; qq < Qn; ++qq) a += sm[OFF_PCG + qq * Mn + tid];
        sm[OFF_WCG + tid] = a;
    }
    {
        int qq = tid >> 4, dblk = tid & 15;
        ull o2[4], kb2[4];
        #pragma unroll
        for (int i = 0; i < 4; ++i) { o2[i] = 0ull; kb2[i] = 0ull; }
        #pragma unroll
        for (int j = 0; j < Mn; ++j) {
            ull pc2 = dup2(sm[OFF_PCG + qq * Mn + j]);
            ulonglong2 vA = *(const ulonglong2*)&sm[OFF_VCG + j * CGP + dblk * 8];
            ulonglong2 vB = *(const ulonglong2*)&sm[OFF_VCG + j * CGP + dblk * 8 + 4];
            ulonglong2 kA = *(const ulonglong2*)&sm[OFF_KCG + j * CGP + dblk * 8];
            ulonglong2 kB = *(const ulonglong2*)&sm[OFF_KCG + j * CGP + dblk * 8 + 4];
            o2[0]  = fma2(pc2, vA.x, o2[0]);  o2[1]  = fma2(pc2, vA.y, o2[1]);
            o2[2]  = fma2(pc2, vB.x, o2[2]);  o2[3]  = fma2(pc2, vB.y, o2[3]);
            kb2[0] = fma2(pc2, kA.x, kb2[0]); kb2[1] = fma2(pc2, kA.y, kb2[1]);
            kb2[2] = fma2(pc2, kB.x, kb2[2]); kb2[3] = fma2(pc2, kB.y, kb2[3]);
        }
        *(ulonglong2*)&sm[OFF_OCG  + qq * Dn + dblk * 8]     = make_ulonglong2(o2[0], o2[1]);
        *(ulonglong2*)&sm[OFF_OCG  + qq * Dn + dblk * 8 + 4] = make_ulonglong2(o2[2], o2[3]);
        *(ulonglong2*)&sm[OFF_KBCG + qq * Dn + dblk * 8]     = make_ulonglong2(kb2[0], kb2[1]);
        *(ulonglong2*)&sm[OFF_KBCG + qq * Dn + dblk * 8 + 4] = make_ulonglong2(kb2[2], kb2[3]);
    }

    // ---- dense scores (fp32 SIMT, exact) ----
    const float* kbase = gk + (size_t)b * Sn * Dn;
    const float* vbase = gv + (size_t)b * Sn * Dn;
    const int qg = tid >> 6;
    const int sl = tid & 63;
    for (int t = 0; t < NCHUNK; ++t) {
        __syncthreads();
        const float4* kg4 = (const float4*)(kbase + (size_t)t * TILE * Dn);
        #pragma unroll
        for (int it = 0; it < 8; ++it) {
            int fidx = tid + it * NT;
            int row = fidx >> 5, c4 = fidx & 31;
            float4 val = kg4[fidx];
            float* dst = &sm[OFF_K32 + row * 129 + c4 * 4];
            dst[0] = val.x; dst[1] = val.y; dst[2] = val.z; dst[3] = val.w;
        }
        __syncthreads();
        ull a01 = 0ull, a23 = 0ull;
        #pragma unroll 8
        for (int d = 0; d < Dn; ++d) {
            ull kv2 = dup2(sm[OFF_K32 + sl * 129 + d]);
            ulonglong2 q2 = *(const ulonglong2*)&sm[OFF_QT + d * 16 + qg * 4];
            a01 = fma2(q2.x, kv2, a01);
            a23 = fma2(q2.y, kv2, a23);
        }
        float2 f01 = unpack2(a01), f23 = unpack2(a23);
        int scol = t * TILE + sl;
        sm[OFF_P + (qg * 4 + 0) * PPITCH + scol] = f01.x * scale;
        sm[OFF_P + (qg * 4 + 1) * PPITCH + scol] = f01.y * scale;
        sm[OFF_P + (qg * 4 + 2) * PPITCH + scol] = f23.x * scale;
        sm[OFF_P + (qg * 4 + 3) * PPITCH + scol] = f23.y * scale;
    }
    __syncthreads();

    // ---- softmax rows + w ----
    #pragma unroll
    for (int r = 0; r < 2; ++r) {
        int qq = wid + r * 8;
        float* row = &sm[OFF_P + qq * PPITCH];
        float m = -1e30f;
        #pragma unroll
        for (int i = 0; i < 16; ++i) m = fmaxf(m, row[lane + 32 * i]);
        #pragma unroll
        for (int o = 16; o > 0; o >>= 1) m = fmaxf(m, __shfl_xor_sync(0xffffffffu, m, o));
        float ss = 0.f;
        float ev[16];
        #pragma unroll
        for (int i = 0; i < 16; ++i) { ev[i] = __expf(row[lane + 32 * i] - m); ss += ev[i]; }
        #pragma unroll
        for (int o = 16; o > 0; o >>= 1) ss += __shfl_xor_sync(0xffffffffu, ss, o);
        float inv = 1.f / ss;
        #pragma unroll
        for (int i = 0; i < 16; ++i) row[lane + 32 * i] = ev[i] * inv;
    }
    __syncthreads();
    for (int s = tid; s < Sn; s += NT) {
        float a = 0.f;
        #pragma unroll
        for (int qq = 0; qq < Qn; ++qq) a += sm[OFF_P + qq * PPITCH + s];
        sm[OFF_W + s] = a;
    }

    // ---- main tensor-core pass ----
    const int grp = lane >> 3, li = lane & 7;
    const int arow = (grp & 1) * 8 + li;
    const int akc  = (grp >> 1) * 8;
    const int brow = (grp >> 1) * 8 + li;
    const int bkc  = (grp & 1) * 8;
    const int m0   = wid * 16;

    float accJ[16][4];
    float accO[2][4], accK[2][4];
    #pragma unroll
    for (int nt = 0; nt < 16; ++nt)
        #pragma unroll
        for (int e = 0; e < 4; ++e) accJ[nt][e] = 0.f;
    #pragma unroll
    for (int nt = 0; nt < 2; ++nt)
        #pragma unroll
        for (int e = 0; e < 4; ++e) { accO[nt][e] = 0.f; accK[nt][e] = 0.f; }

    for (int c = 0; c < NCHUNK; ++c) {
        const int s0 = c * TILE;
        __syncthreads();   // tiles + K32/V32 free from previous chunk
        // ---- stage K and V together (MLP 16) ----
        {
            const float4* kg4 = (const float4*)(kbase + (size_t)s0 * Dn);
            const float4* vg4 = (const float4*)(vbase + (size_t)s0 * Dn);
            #pragma unroll
            for (int it = 0; it < 8; ++it) {
                int fidx = tid + it * NT;
                int row = fidx >> 5, c4 = fidx & 31;
                float4 kv = kg4[fidx];
                float4 vv = vg4[fidx];
                float* dk = &sm[OFF_K32 + row * 129 + c4 * 4];
                float* dv = &sm[OFF_V32 + row * 129 + c4 * 4];
                dk[0] = kv.x; dk[1] = kv.y; dk[2] = kv.z; dk[3] = kv.w;
                dv[0] = vv.x; dv[1] = vv.y; dv[2] = vv.z; dv[3] = vv.w;
            }
        }
        __syncthreads();
        // ---- convert: K -> KH + WKH ; V -> VH/VL ; p -> PH/PL ----
        {
            float w0 = sm[OFF_W + s0 + 2 * lane];
            float w1 = sm[OFF_W + s0 + 2 * lane + 1];
            #pragma unroll
            for (int r = 0; r < 16; ++r) {
                int d = wid * 16 + r;
                uint32_t sw = swz((uint32_t)(d * 128 + lane * 4));
                float ka = sm[OFF_K32 + (2 * lane) * 129 + d];
                float kb = sm[OFF_K32 + (2 * lane + 1) * 129 + d];
                *(uint32_t*)(smc + OFF_KH * 4 + sw)  = cvt2h(ka, kb);
                *(uint32_t*)(smc + OFF_WKH * 4 + sw) = cvt2h(ka * w0, kb * w1);
                float va = sm[OFF_V32 + (2 * lane) * 129 + d];
                float vb = sm[OFF_V32 + (2 * lane + 1) * 129 + d];
                uint32_t hi, lo;
                split2h(va, vb, hi, lo);
                *(uint32_t*)(smc + OFF_VH * 4 + sw) = hi;
                *(uint32_t*)(smc + OFF_VL * 4 + sw) = lo;
            }
            #pragma unroll
            for (int rr = 0; rr < 2; ++rr) {
                int qq = wid * 2 + rr;
                float p0 = sm[OFF_P + qq * PPITCH + s0 + 2 * lane];
                float p1 = sm[OFF_P + qq * PPITCH + s0 + 2 * lane + 1];
                uint32_t sw = swz((uint32_t)(qq * 128 + lane * 4));
                uint32_t hi, lo;
                split2h(p0, p1, hi, lo);
                *(uint32_t*)(smc + OFF_PH * 4 + sw) = hi;
                *(uint32_t*)(smc + OFF_PL * 4 + sw) = lo;
            }
        }
        __syncthreads();

        // ---- fragments + MMAs ----
        uint32_t vah[4][4], valo[4][4];
        #pragma unroll
        for (int k = 0; k < 4; ++k) {
            uint32_t addr = swz((uint32_t)((m0 + arow) * 128 + (k * 16 + akc) * 2));
            ldsm4(vah[k][0], vah[k][1], vah[k][2], vah[k][3], smb + OFF_VH * 4 + addr);
            ldsm4(valo[k][0], valo[k][1], valo[k][2], valo[k][3], smb + OFF_VL * 4 + addr);
        }
        // out (3-combo) / kbar (2-combo: Kh*(Ph+Pl))
        #pragma unroll
        for (int k = 0; k < 4; ++k) {
            uint32_t ph[4], pl[4], kah[4];
            uint32_t pa = swz((uint32_t)(brow * 128 + (k * 16 + bkc) * 2));
            ldsm4(ph[0], ph[1], ph[2], ph[3], smb + OFF_PH * 4 + pa);
            ldsm4(pl[0], pl[1], pl[2], pl[3], smb + OFF_PL * 4 + pa);
            uint32_t ka = swz((uint32_t)((m0 + arow) * 128 + (k * 16 + akc) * 2));
            ldsm4(kah[0], kah[1], kah[2], kah[3], smb + OFF_KH * 4 + ka);
            mma16816(accO[0], vah[k], ph[0], ph[1]);
            mma16816(accO[0], vah[k], pl[0], pl[1]);
            mma16816(accO[0], valo[k], ph[0], ph[1]);
            mma16816(accO[1], vah[k], ph[2], ph[3]);
            mma16816(accO[1], vah[k], pl[2], pl[3]);
            mma16816(accO[1], valo[k], ph[2], ph[3]);
            mma16816(accK[0], kah, ph[0], ph[1]);
            mma16816(accK[0], kah, pl[0], pl[1]);
            mma16816(accK[1], kah, ph[2], ph[3]);
            mma16816(accK[1], kah, pl[2], pl[3]);
        }
        // J1 (2-combo: Vh*Wh + Vl*Wh)
        #pragma unroll
        for (int k = 0; k < 4; ++k) {
            #pragma unroll
            for (int np = 0; np < 8; ++np) {
                uint32_t bh[4];
                uint32_t ba = swz((uint32_t)((np * 16 + brow) * 128 + (k * 16 + bkc) * 2));
                ldsm4(bh[0], bh[1], bh[2], bh[3], smb + OFF_WKH * 4 + ba);
                mma16816(accJ[np * 2], vah[k], bh[0], bh[1]);
                mma16816(accJ[np * 2], valo[k], bh[0], bh[1]);
                mma16816(accJ[np * 2 + 1], vah[k], bh[2], bh[3]);
                mma16816(accJ[np * 2 + 1], valo[k], bh[2], bh[3]);
            }
        }
    }
    __syncthreads();

    // ---- write out^T / kbar^T to smem as [q][dv] ----
    {
        int r = lane >> 2, cc2 = (lane & 3) * 2;
        #pragma unroll
        for (int nt = 0; nt < 2; ++nt) {
            int qq = nt * 8 + cc2;
            sm[OFF_OUT  + qq * Dn + m0 + r]           = accO[nt][0];
            sm[OFF_OUT  + (qq + 1) * Dn + m0 + r]     = accO[nt][1];
            sm[OFF_OUT  + qq * Dn + m0 + r + 8]       = accO[nt][2];
            sm[OFF_OUT  + (qq + 1) * Dn + m0 + r + 8] = accO[nt][3];
            sm[OFF_KBAR + qq * Dn + m0 + r]           = accK[nt][0];
            sm[OFF_KBAR + (qq + 1) * Dn + m0 + r]     = accK[nt][1];
            sm[OFF_KBAR + qq * Dn + m0 + r + 8]       = accK[nt][2];
            sm[OFF_KBAR + (qq + 1) * Dn + m0 + r + 8] = accK[nt][3];
        }
    }
    __syncthreads();

    // ---- epilogue: J2 + cg jacobian + clip + cosine ----
    const int r = lane >> 2, cc2 = (lane & 3) * 2;
    float o0a[16], o1a[16], c0a[16], c1a[16], vc0[8], vc1[8];
    #pragma unroll
    for (int q = 0; q < 16; ++q) {
        o0a[q] = sm[OFF_OUT + q * Dn + m0 + r];
        o1a[q] = sm[OFF_OUT + q * Dn + m0 + r + 8];
        c0a[q] = sm[OFF_OCG + q * Dn + m0 + r];
        c1a[q] = sm[OFF_OCG + q * Dn + m0 + r + 8];
    }
    #pragma unroll
    for (int j = 0; j < 8; ++j) {
        float wc = sm[OFF_WCG + j];
        vc0[j] = wc * sm[OFF_VCG + j * CGP + m0 + r];
        vc1[j] = wc * sm[OFF_VCG + j * CGP + m0 + r + 8];
    }

    float dd = 0.f, ccv = 0.f, dc = 0.f;
    #pragma unroll
    for (int nt = 0; nt < 16; ++nt) {
        ull jd0, jd1, jc0, jc1;
        asm("mov.b64 %0, {%1, %2};" : "=l"(jd0) : "f"(accJ[nt][0]), "f"(accJ[nt][1]));
        asm("mov.b64 %0, {%1, %2};" : "=l"(jd1) : "f"(accJ[nt][2]), "f"(accJ[nt][3]));
        jc0 = 0ull; jc1 = 0ull;
        int colb = nt * 8 + cc2;
        #pragma unroll
        for (int q = 0; q < 16; ++q) {
            ull kbp = *(const ull*)&sm[OFF_KBAR + q * Dn + colb];
            jd0 = fma2(dup2(-o0a[q]), kbp, jd0);
            jd1 = fma2(dup2(-o1a[q]), kbp, jd1);
        }
        #pragma unroll
        for (int j = 0; j < 8; ++j) {
            ull kcp = *(const ull*)&sm[OFF_KCG + j * CGP + colb];
            jc0 = fma2(dup2(vc0[j]), kcp, jc0);
            jc1 = fma2(dup2(vc1[j]), kcp, jc1);
        }
        #pragma unroll
        for (int q = 0; q < 16; ++q) {
            ull kbp = *(const ull*)&sm[OFF_KBCG + q * Dn + colb];
            jc0 = fma2(dup2(-c0a[q]), kbp, jc0);
            jc1 = fma2(dup2(-c1a[q]), kbp, jc1);
        }
        float2 d0 = unpack2(jd0), d1 = unpack2(jd1);
        float2 g0 = unpack2(jc0), g1 = unpack2(jc1);
        float jdv[4] = {d0.x, d0.y, d1.x, d1.y};
        float jcv[4] = {g0.x, g0.y, g1.x, g1.y};
        #pragma unroll
        for (int e = 0; e < 4; ++e) {
            float a = clip50(jdv[e] * scale);
            float g = clip50(jcv[e] * scale);
            dd  = fmaf(a, a, dd);
            ccv = fmaf(g, g, ccv);
            dc  = fmaf(a, g, dc);
        }
    }
    float cons = 0.f;
    #pragma unroll
    for (int i = 0; i < 8; ++i) {
        float dif = sm[OFF_OUT + tid * 8 + i] - sm[OFF_OCG + tid * 8 + i];
        cons = fmaf(dif, dif, cons);
    }

    #pragma unroll
    for (int o = 16; o > 0; o >>= 1) {
        dd   += __shfl_xor_sync(0xffffffffu, dd,   o);
        ccv  += __shfl_xor_sync(0xffffffffu, ccv,  o);
        dc   += __shfl_xor_sync(0xffffffffu, dc,   o);
        cons += __shfl_xor_sync(0xffffffffu, cons, o);
    }
    if (lane == 0) {
        sm[OFF_RED + wid * 4 + 0] = dd;
        sm[OFF_RED + wid * 4 + 1] = ccv;
        sm[OFF_RED + wid * 4 + 2] = dc;
        sm[OFF_RED + wid * 4 + 3] = cons;
    }
    __syncthreads();
    if (tid == 0) {
        float DD = 0.f, CC = 0.f, DC = 0.f, CO = 0.f;
        #pragma unroll
        for (int w8 = 0; w8 < 8; ++w8) {
            DD += sm[OFF_RED + w8 * 4 + 0];
            CC += sm[OFF_RED + w8 * 4 + 1];
            DC += sm[OFF_RED + w8 * 4 + 2];
            CO += sm[OFF_RED + w8 * 4 + 3];
        }
        float cosv = DC / (sqrtf(DD) * sqrtf(CC) + 1e-8f);
        g_losses[b] = (1.0f - cosv) + CO * (1.0f / (float)(Qn * Dn));
    }
}

__global__ void fml_reduce(float* out) {
    int lane = threadIdx.x;
    float a = 0.f;
    #pragma unroll
    for (int i = 0; i < 8; ++i) a += g_losses[lane * 8 + i];
    #pragma unroll
    for (int o = 16; o > 0; o >>= 1) a += __shfl_xor_sync(0xffffffffu, a, o);
    if (lane == 0) out[0] = a * (1.0f / (float)Bn);
}

extern "C" void kernel_launch(void* const* d_in, const int* in_sizes, int n_in,
                              void* d_out, int out_size)
{
    const float* q   = (const float*)d_in[0];
    const float* k   = (const float*)d_in[1];
    const float* v   = (const float*)d_in[2];
    const float* kcg = (const float*)d_in[3];
    const float* vcg = (const float*)d_in[4];

    cudaFuncSetAttribute(fml_kernel, cudaFuncAttributeMaxDynamicSharedMemorySize,
                         SMEM_FLOATS * (int)sizeof(float));
    fml_kernel<<<Bn, NT, SMEM_FLOATS * sizeof(float)>>>(q, k, v, kcg, vcg);
    fml_reduce<<<1, 32>>>((float*)d_out);
}

// round 10
// speedup vs baseline: 1.0080x; 1.0080x over previous
#include <cuda_runtime.h>
#include <cuda_fp16.h>
#include <cstdint>

#define Bn 256
#define Qn 16
#define Sn 512
#define Mn 8
#define Dn 128
#define NT 512
#define TILE 64
#define NCHUNK 8
#define PPITCH 520
#define CGP 132

typedef unsigned long long ull;

// ---- shared memory layout (float offsets) ----
#define OFF_QT   0          // qT[128][16]
#define OFF_P    2048       // p[16][520]
#define OFF_W    10368      // w[512]
#define OFF_OUT  10880      // out [q][128]
#define OFF_KBAR 12928      // kbar [q][128]
#define OFF_OCG  14976      // cg out [q][128]
#define OFF_KBCG 17024      // cg kbar [q][128]
#define OFF_KCG  19072      // kcg[8][132]
#define OFF_VCG  20128      // vcg[8][132]
#define OFF_PCG  21184      // p_cg[16][8]
#define OFF_WCG  21312      // w_cg[8]
#define OFF_RED  21320      // 16 warps * 4 = 64
#define OFF_K32  21440      // fp32 stage K [64][129] -> 29696
#define OFF_V32  29696      // fp32 stage V [64][129] -> 37952
// fp16 tiles [128 d][64 s] = 4096 floats each, 128B rows, swizzled (32-float aligned)
#define OFF_VH   37952
#define OFF_VL   42048
#define OFF_WKH  46144
#define OFF_KH   50240
#define OFF_PH   54336      // p fp16 [16 q][64 s] = 512 floats
#define OFF_PL   54848
#define SMEM_FLOATS 55360   // 221440 bytes

__device__ float g_losses[Bn];

__device__ __forceinline__ float clip50(float x) {
    return fminf(fmaxf(x, -50.0f), 50.0f);
}
__device__ __forceinline__ ull dup2(float x) {
    ull r; asm("mov.b64 %0, {%1, %1};" : "=l"(r) : "f"(x)); return r;
}
__device__ __forceinline__ ull fma2(ull a, ull b, ull c) {
    ull d; asm("fma.rn.f32x2 %0, %1, %2, %3;" : "=l"(d) : "l"(a), "l"(b), "l"(c)); return d;
}
__device__ __forceinline__ float2 unpack2(ull p) {
    float2 f; asm("mov.b64 {%0, %1}, %2;" : "=f"(f.x), "=f"(f.y) : "l"(p)); return f;
}
__device__ __forceinline__ uint32_t smem_u32(const void* p) {
    uint32_t a;
    asm("{ .reg .u64 t; cvta.to.shared.u64 t, %1; cvt.u32.u64 %0, t; }" : "=r"(a) : "l"(p));
    return a;
}
__device__ __forceinline__ void split2h(float f0, float f1, uint32_t& hi, uint32_t& lo) {
    __half2 h = __floats2half2_rn(f0, f1);
    float2 hf = __half22float2(h);
    __half2 l = __floats2half2_rn(f0 - hf.x, f1 - hf.y);
    hi = *(uint32_t*)&h;
    lo = *(uint32_t*)&l;
}
__device__ __forceinline__ uint32_t cvt2h(float f0, float f1) {
    __half2 h = __floats2half2_rn(f0, f1);
    return *(uint32_t*)&h;
}
__device__ __forceinline__ uint32_t swz(uint32_t off) { return off ^ ((off >> 3) & 0x70); }

__device__ __forceinline__ void ldsm4(uint32_t& r0, uint32_t& r1, uint32_t& r2, uint32_t& r3, uint32_t a) {
    asm volatile("ldmatrix.sync.aligned.m8n8.x4.shared.b16 {%0,%1,%2,%3}, [%4];"
                 : "=r"(r0), "=r"(r1), "=r"(r2), "=r"(r3) : "r"(a));
}
__device__ __forceinline__ void mma16816(float* d, const uint32_t* a, uint32_t b0, uint32_t b1) {
    asm volatile("mma.sync.aligned.m16n8k16.row.col.f32.f16.f16.f32 "
                 "{%0,%1,%2,%3}, {%4,%5,%6,%7}, {%8,%9}, {%0,%1,%2,%3};"
                 : "+f"(d[0]), "+f"(d[1]), "+f"(d[2]), "+f"(d[3])
                 : "r"(a[0]), "r"(a[1]), "r"(a[2]), "r"(a[3]), "r"(b0), "r"(b1));
}

__global__ void __launch_bounds__(NT, 1)
fml_kernel(const float* __restrict__ gq, const float* __restrict__ gk,
           const float* __restrict__ gv, const float* __restrict__ gkcg,
           const float* __restrict__ gvcg)
{
    extern __shared__ float sm[];
    char* smc = (char*)sm;
    const int b   = blockIdx.x;
    const int tid = threadIdx.x;
    const int wid = tid >> 5, lane = tid & 31;
    const float scale = 0.088388347648318447f;
    const uint32_t smb = smem_u32(sm);

    // ---- load qT [d][16] and cg tensors ----
    const float* qb = gq + (size_t)b * Qn * Dn;
    for (int i = tid; i < Qn * Dn; i += NT) {
        int qq = i >> 7, d = i & 127;
        sm[OFF_QT + d * 16 + qq] = qb[i];
    }
    const float* kcb = gkcg + (size_t)b * Mn * Dn;
    const float* vcb = gvcg + (size_t)b * Mn * Dn;
    for (int i = tid; i < Mn * Dn; i += NT) {
        int j = i >> 7, d = i & 127;
        sm[OFF_KCG + j * CGP + d] = kcb[i];
        sm[OFF_VCG + j * CGP + d] = vcb[i];
    }
    __syncthreads();

    // ---- cg scores / softmax / w_cg / out / kbar (exact SIMT) ----
    if (tid < Qn * Mn) {
        int qq = tid >> 3, j = tid & 7;
        float acc = 0.f;
        #pragma unroll 8
        for (int d = 0; d < Dn; ++d)
            acc = fmaf(sm[OFF_QT + d * 16 + qq], sm[OFF_KCG + j * CGP + d], acc);
        sm[OFF_PCG + qq * Mn + j] = acc * scale;
    }
    __syncthreads();
    if (tid < Qn) {
        float m = -1e30f;
        #pragma unroll
        for (int j = 0; j < Mn; ++j) m = fmaxf(m, sm[OFF_PCG + tid * Mn + j]);
        float ss = 0.f;
        #pragma unroll
        for (int j = 0; j < Mn; ++j) {
            float e = __expf(sm[OFF_PCG + tid * Mn + j] - m);
            sm[OFF_PCG + tid * Mn + j] = e; ss += e;
        }
        float inv = 1.f / ss;
        #pragma unroll
        for (int j = 0; j < Mn; ++j) sm[OFF_PCG + tid * Mn + j] *= inv;
    }
    __syncthreads();
    if (tid < Mn) {
        float a = 0.f;
        #pragma unroll
        for (int qq = 0; qq < Qn; ++qq) a += sm[OFF_PCG + qq * Mn + tid];
        sm[OFF_WCG + tid] = a;
    }
    if (tid < 256) {
        int qq = tid >> 4, dblk = tid & 15;
        ull o2[4], kb2[4];
        #pragma unroll
        for (int i = 0; i < 4; ++i) { o2[i] = 0ull; kb2[i] = 0ull; }
        #pragma unroll
        for (int j = 0; j < Mn; ++j) {
            ull pc2 = dup2(sm[OFF_PCG + qq * Mn + j]);
            ulonglong2 vA = *(const ulonglong2*)&sm[OFF_VCG + j * CGP + dblk * 8];
            ulonglong2 vB = *(const ulonglong2*)&sm[OFF_VCG + j * CGP + dblk * 8 + 4];
            ulonglong2 kA = *(const ulonglong2*)&sm[OFF_KCG + j * CGP + dblk * 8];
            ulonglong2 kB = *(const ulonglong2*)&sm[OFF_KCG + j * CGP + dblk * 8 + 4];
            o2[0]  = fma2(pc2, vA.x, o2[0]);  o2[1]  = fma2(pc2, vA.y, o2[1]);
            o2[2]  = fma2(pc2, vB.x, o2[2]);  o2[3]  = fma2(pc2, vB.y, o2[3]);
            kb2[0] = fma2(pc2, kA.x, kb2[0]); kb2[1] = fma2(pc2, kA.y, kb2[1]);
            kb2[2] = fma2(pc2, kB.x, kb2[2]); kb2[3] = fma2(pc2, kB.y, kb2[3]);
        }
        *(ulonglong2*)&sm[OFF_OCG  + qq * Dn + dblk * 8]     = make_ulonglong2(o2[0], o2[1]);
        *(ulonglong2*)&sm[OFF_OCG  + qq * Dn + dblk * 8 + 4] = make_ulonglong2(o2[2], o2[3]);
        *(ulonglong2*)&sm[OFF_KBCG + qq * Dn + dblk * 8]     = make_ulonglong2(kb2[0], kb2[1]);
        *(ulonglong2*)&sm[OFF_KBCG + qq * Dn + dblk * 8 + 4] = make_ulonglong2(kb2[2], kb2[3]);
    }

    // ---- dense scores (fp32 SIMT, exact): 8 q-groups x 64 s ----
    const float* kbase = gk + (size_t)b * Sn * Dn;
    const float* vbase = gv + (size_t)b * Sn * Dn;
    const int qg = tid >> 6;        // 0..7 (2 queries each)
    const int sl = tid & 63;
    for (int t = 0; t < NCHUNK; ++t) {
        __syncthreads();
        const float4* kg4 = (const float4*)(kbase + (size_t)t * TILE * Dn);
        #pragma unroll
        for (int it = 0; it < 4; ++it) {
            int fidx = tid + it * NT;
            int row = fidx >> 5, c4 = fidx & 31;
            float4 val = kg4[fidx];
            float* dst = &sm[OFF_K32 + row * 129 + c4 * 4];
            dst[0] = val.x; dst[1] = val.y; dst[2] = val.z; dst[3] = val.w;
        }
        __syncthreads();
        ull a01 = 0ull;
        #pragma unroll 8
        for (int d = 0; d < Dn; ++d) {
            ull kv2 = dup2(sm[OFF_K32 + sl * 129 + d]);
            ull q2 = *(const ull*)&sm[OFF_QT + d * 16 + qg * 2];
            a01 = fma2(q2, kv2, a01);
        }
        float2 f01 = unpack2(a01);
        int scol = t * TILE + sl;
        sm[OFF_P + (qg * 2 + 0) * PPITCH + scol] = f01.x * scale;
        sm[OFF_P + (qg * 2 + 1) * PPITCH + scol] = f01.y * scale;
    }
    __syncthreads();

    // ---- softmax: one row per warp (16 warps = 16 rows) ----
    {
        float* row = &sm[OFF_P + wid * PPITCH];
        float m = -1e30f;
        #pragma unroll
        for (int i = 0; i < 16; ++i) m = fmaxf(m, row[lane + 32 * i]);
        #pragma unroll
        for (int o = 16; o > 0; o >>= 1) m = fmaxf(m, __shfl_xor_sync(0xffffffffu, m, o));
        float ss = 0.f;
        float ev[16];
        #pragma unroll
        for (int i = 0; i < 16; ++i) { ev[i] = __expf(row[lane + 32 * i] - m); ss += ev[i]; }
        #pragma unroll
        for (int o = 16; o > 0; o >>= 1) ss += __shfl_xor_sync(0xffffffffu, ss, o);
        float inv = 1.f / ss;
        #pragma unroll
        for (int i = 0; i < 16; ++i) row[lane + 32 * i] = ev[i] * inv;
    }
    __syncthreads();
    {
        int s = tid;    // 512 threads = 512 s
        float a = 0.f;
        #pragma unroll
        for (int qq = 0; qq < Qn; ++qq) a += sm[OFF_P + qq * PPITCH + s];
        sm[OFF_W + s] = a;
    }

    // ---- main tensor-core pass: 16 warps, grid 8m x 2n ----
    const int grp = lane >> 3, li = lane & 7;
    const int arow = (grp & 1) * 8 + li;
    const int akc  = (grp >> 1) * 8;
    const int brow = (grp >> 1) * 8 + li;
    const int bkc  = (grp & 1) * 8;
    const int mw   = wid & 7;
    const int m0   = mw * 16;        // this warp's 16 d-rows
    const int nj   = wid >> 3;       // col half: nj*64

    float accJ[8][4];
    float accO[2][4];                // nj==0: out ; nj==1: kbar
    #pragma unroll
    for (int nt = 0; nt < 8; ++nt)
        #pragma unroll
        for (int e = 0; e < 4; ++e) accJ[nt][e] = 0.f;
    #pragma unroll
    for (int nt = 0; nt < 2; ++nt)
        #pragma unroll
        for (int e = 0; e < 4; ++e) accO[nt][e] = 0.f;

    for (int c = 0; c < NCHUNK; ++c) {
        const int s0 = c * TILE;
        __syncthreads();
        // ---- stage K and V together ----
        {
            const float4* kg4 = (const float4*)(kbase + (size_t)s0 * Dn);
            const float4* vg4 = (const float4*)(vbase + (size_t)s0 * Dn);
            #pragma unroll
            for (int it = 0; it < 4; ++it) {
                int fidx = tid + it * NT;
                int row = fidx >> 5, c4 = fidx & 31;
                float4 kv = kg4[fidx];
                float4 vv = vg4[fidx];
                float* dk = &sm[OFF_K32 + row * 129 + c4 * 4];
                float* dv = &sm[OFF_V32 + row * 129 + c4 * 4];
                dk[0] = kv.x; dk[1] = kv.y; dk[2] = kv.z; dk[3] = kv.w;
                dv[0] = vv.x; dv[1] = vv.y; dv[2] = vv.z; dv[3] = vv.w;
            }
        }
        __syncthreads();
        // ---- convert: K -> KH + WKH ; V -> VH/VL (8 d-rows/warp) ; p (1 q-row/warp) ----
        {
            float w0 = sm[OFF_W + s0 + 2 * lane];
            float w1 = sm[OFF_W + s0 + 2 * lane + 1];
            #pragma unroll
            for (int r = 0; r < 8; ++r) {
                int d = wid * 8 + r;
                uint32_t sw = swz((uint32_t)(d * 128 + lane * 4));
                float ka = sm[OFF_K32 + (2 * lane) * 129 + d];
                float kb = sm[OFF_K32 + (2 * lane + 1) * 129 + d];
                *(uint32_t*)(smc + OFF_KH * 4 + sw)  = cvt2h(ka, kb);
                *(uint32_t*)(smc + OFF_WKH * 4 + sw) = cvt2h(ka * w0, kb * w1);
                float va = sm[OFF_V32 + (2 * lane) * 129 + d];
                float vb = sm[OFF_V32 + (2 * lane + 1) * 129 + d];
                uint32_t hi, lo;
                split2h(va, vb, hi, lo);
                *(uint32_t*)(smc + OFF_VH * 4 + sw) = hi;
                *(uint32_t*)(smc + OFF_VL * 4 + sw) = lo;
            }
            {
                int qq = wid;
                float p0 = sm[OFF_P + qq * PPITCH + s0 + 2 * lane];
                float p1 = sm[OFF_P + qq * PPITCH + s0 + 2 * lane + 1];
                uint32_t sw = swz((uint32_t)(qq * 128 + lane * 4));
                uint32_t hi, lo;
                split2h(p0, p1, hi, lo);
                *(uint32_t*)(smc + OFF_PH * 4 + sw) = hi;
                *(uint32_t*)(smc + OFF_PL * 4 + sw) = lo;
            }
        }
        __syncthreads();

        // ---- fragments + MMAs (V fragments loaded per-k to limit registers) ----
        #pragma unroll
        for (int k = 0; k < 4; ++k) {
            uint32_t vah[4], valo[4];
            uint32_t addr = swz((uint32_t)((m0 + arow) * 128 + (k * 16 + akc) * 2));
            ldsm4(vah[0], vah[1], vah[2], vah[3], smb + OFF_VH * 4 + addr);
            ldsm4(valo[0], valo[1], valo[2], valo[3], smb + OFF_VL * 4 + addr);

            uint32_t ph[4], pl[4];
            uint32_t pa = swz((uint32_t)(brow * 128 + (k * 16 + bkc) * 2));
            ldsm4(ph[0], ph[1], ph[2], ph[3], smb + OFF_PH * 4 + pa);
            ldsm4(pl[0], pl[1], pl[2], pl[3], smb + OFF_PL * 4 + pa);

            if (nj == 0) {
                // out = V * p (3-combo)
                mma16816(accO[0], vah, ph[0], ph[1]);
                mma16816(accO[0], vah, pl[0], pl[1]);
                mma16816(accO[0], valo, ph[0], ph[1]);
                mma16816(accO[1], vah, ph[2], ph[3]);
                mma16816(accO[1], vah, pl[2], pl[3]);
                mma16816(accO[1], valo, ph[2], ph[3]);
            } else {
                // kbar = K * p (2-combo: Kh*(Ph+Pl))
                uint32_t kah[4];
                ldsm4(kah[0], kah[1], kah[2], kah[3], smb + OFF_KH * 4 + addr);
                mma16816(accO[0], kah, ph[0], ph[1]);
                mma16816(accO[0], kah, pl[0], pl[1]);
                mma16816(accO[1], kah, ph[2], ph[3]);
                mma16816(accO[1], kah, pl[2], pl[3]);
            }
            // J1 (2-combo): cols nj*64 .. nj*64+63
            #pragma unroll
            for (int np = 0; np < 4; ++np) {
                uint32_t bh[4];
                uint32_t ba = swz((uint32_t)((nj * 64 + np * 16 + brow) * 128 + (k * 16 + bkc) * 2));
                ldsm4(bh[0], bh[1], bh[2], bh[3], smb + OFF_WKH * 4 + ba);
                mma16816(accJ[np * 2], vah, bh[0], bh[1]);
                mma16816(accJ[np * 2], valo, bh[0], bh[1]);
                mma16816(accJ[np * 2 + 1], vah, bh[2], bh[3]);
                mma16816(accJ[np * 2 + 1], valo, bh[2], bh[3]);
            }
        }
    }
    __syncthreads();

    // ---- write out^T (nj==0) / kbar^T (nj==1) to smem [q][d] ----
    {
        int r = lane >> 2, cc2 = (lane & 3) * 2;
        int base = (nj == 0) ? OFF_OUT : OFF_KBAR;
        #pragma unroll
        for (int nt = 0; nt < 2; ++nt) {
            int qq = nt * 8 + cc2;
            sm[base + qq * Dn + m0 + r]           = accO[nt][0];
            sm[base + (qq + 1) * Dn + m0 + r]     = accO[nt][1];
            sm[base + qq * Dn + m0 + r + 8]       = accO[nt][2];
            sm[base + (qq + 1) * Dn + m0 + r + 8] = accO[nt][3];
        }
    }
    __syncthreads();

    // ---- epilogue: J2 + cg jacobian + clip + cosine ----
    const int r = lane >> 2, cc2 = (lane & 3) * 2;
    float o0a[16], o1a[16], c0a[16], c1a[16], vc0[8], vc1[8];
    #pragma unroll
    for (int q = 0; q < 16; ++q) {
        o0a[q] = sm[OFF_OUT + q * Dn + m0 + r];
        o1a[q] = sm[OFF_OUT + q * Dn + m0 + r + 8];
        c0a[q] = sm[OFF_OCG + q * Dn + m0 + r];
        c1a[q] = sm[OFF_OCG + q * Dn + m0 + r + 8];
    }
    #pragma unroll
    for (int j = 0; j < 8; ++j) {
        float wc = sm[OFF_WCG + j];
        vc0[j] = wc * sm[OFF_VCG + j * CGP + m0 + r];
        vc1[j] = wc * sm[OFF_VCG + j * CGP + m0 + r + 8];
    }

    float dd = 0.f, ccv = 0.f, dc = 0.f;
    #pragma unroll
    for (int nt = 0; nt < 8; ++nt) {
        ull jd0, jd1, jc0, jc1;
        asm("mov.b64 %0, {%1, %2};" : "=l"(jd0) : "f"(accJ[nt][0]), "f"(accJ[nt][1]));
        asm("mov.b64 %0, {%1, %2};" : "=l"(jd1) : "f"(accJ[nt][2]), "f"(accJ[nt][3]));
        jc0 = 0ull; jc1 = 0ull;
        int colb = nj * 64 + nt * 8 + cc2;
        #pragma unroll
        for (int q = 0; q < 16; ++q) {
            ull kbp = *(const ull*)&sm[OFF_KBAR + q * Dn + colb];
            jd0 = fma2(dup2(-o0a[q]), kbp, jd0);
            jd1 = fma2(dup2(-o1a[q]), kbp, jd1);
        }
        #pragma unroll
        for (int j = 0; j < 8; ++j) {
            ull kcp = *(const ull*)&sm[OFF_KCG + j * CGP + colb];
            jc0 = fma2(dup2(vc0[j]), kcp, jc0);
            jc1 = fma2(dup2(vc1[j]), kcp, jc1);
        }
        #pragma unroll
        for (int q = 0; q < 16; ++q) {
            ull kbp = *(const ull*)&sm[OFF_KBCG + q * Dn + colb];
            jc0 = fma2(dup2(-c0a[q]), kbp, jc0);
            jc1 = fma2(dup2(-c1a[q]), kbp, jc1);
        }
        float2 d0 = unpack2(jd0), d1 = unpack2(jd1);
        float2 g0 = unpack2(jc0), g1 = unpack2(jc1);
        float jdv[4] = {d0.x, d0.y, d1.x, d1.y};
        float jcv[4] = {g0.x, g0.y, g1.x, g1.y};
        #pragma unroll
        for (int e = 0; e < 4; ++e) {
            float a = clip50(jdv[e] * scale);
            float g = clip50(jcv[e] * scale);
            dd  = fmaf(a, a, dd);
            ccv = fmaf(g, g, ccv);
            dc  = fmaf(a, g, dc);
        }
    }
    float cons = 0.f;
    #pragma unroll
    for (int i = 0; i < 4; ++i) {
        float dif = sm[OFF_OUT + tid * 4 + i] - sm[OFF_OCG + tid * 4 + i];
        cons = fmaf(dif, dif, cons);
    }

    #pragma unroll
    for (int o = 16; o > 0; o >>= 1) {
        dd   += __shfl_xor_sync(0xffffffffu, dd,   o);
        ccv  += __shfl_xor_sync(0xffffffffu, ccv,  o);
        dc   += __shfl_xor_sync(0xffffffffu, dc,   o);
        cons += __shfl_xor_sync(0xffffffffu, cons, o);
    }
    if (lane == 0) {
        sm[OFF_RED + wid * 4 + 0] = dd;
        sm[OFF_RED + wid * 4 + 1] = ccv;
        sm[OFF_RED + wid * 4 + 2] = dc;
        sm[OFF_RED + wid * 4 + 3] = cons;
    }
    __syncthreads();
    if (tid == 0) {
        float DD = 0.f, CC = 0.f, DC = 0.f, CO = 0.f;
        #pragma unroll
        for (int w8 = 0; w8 < 16; ++w8) {
            DD += sm[OFF_RED + w8 * 4 + 0];
            CC += sm[OFF_RED + w8 * 4 + 1];
            DC += sm[OFF_RED + w8 * 4 + 2];
            CO += sm[OFF_RED + w8 * 4 + 3];
        }
        float cosv = DC / (sqrtf(DD) * sqrtf(CC) + 1e-8f);
        g_losses[b] = (1.0f - cosv) + CO * (1.0f / (float)(Qn * Dn));
    }
}

__global__ void fml_reduce(float* out) {
    int lane = threadIdx.x;
    float a = 0.f;
    #pragma unroll
    for (int i = 0; i < 8; ++i) a += g_losses[lane * 8 + i];
    #pragma unroll
    for (int o = 16; o > 0; o >>= 1) a += __shfl_xor_sync(0xffffffffu, a, o);
    if (lane == 0) out[0] = a * (1.0f / (float)Bn);
}

extern "C" void kernel_launch(void* const* d_in, const int* in_sizes, int n_in,
                              void* d_out, int out_size)
{
    const float* q   = (const float*)d_in[0];
    const float* k   = (const float*)d_in[1];
    const float* v   = (const float*)d_in[2];
    const float* kcg = (const float*)d_in[3];
    const float* vcg = (const float*)d_in[4];

    cudaFuncSetAttribute(fml_kernel, cudaFuncAttributeMaxDynamicSharedMemorySize,
                         SMEM_FLOATS * (int)sizeof(float));
    fml_kernel<<<Bn, NT, SMEM_FLOATS * sizeof(float)>>>(q, k, v, kcg, vcg);
    fml_reduce<<<1, 32>>>((float*)d_out);
}

// round 11
// speedup vs baseline: 1.1808x; 1.1714x over previous
#include <cuda_runtime.h>
#include <cuda_fp16.h>
#include <cstdint>

#define Bn 256
#define Qn 16
#define Sn 512
#define Mn 8
#define Dn 128
#define NT 512
#define TILE 64
#define NCHUNK 8
#define PPITCH 520
#define CGP 132
#define TPITCH 272   // bytes per s-row in fp16 [s][d] tiles (256 data + 16 pad)

typedef unsigned long long ull;

// ---- shared memory layout (float offsets) ----
#define OFF_QT   0          // qT[128][16]
#define OFF_P    2048       // p[16][520]
#define OFF_W    10368      // w[512]
#define OFF_OUT  10880      // out [q][128]
#define OFF_KBAR 12928      // kbar [q][128]
#define OFF_OCG  14976      // cg out [q][128]
#define OFF_KBCG 17024      // cg kbar [q][128]
#define OFF_KCG  19072      // kcg[8][132]
#define OFF_VCG  20128      // vcg[8][132]
#define OFF_PCG  21184      // p_cg[16][8]
#define OFF_WCG  21312      // w_cg[8]
#define OFF_RED  21320      // 16 warps * 4 = 64
#define OFF_K32  21440      // fp32 stage K [64][129] (scores only) -> 29696
// fp16 [s][d] tiles: 64 rows x 272B = 4352 floats each
#define OFF_VH   29696
#define OFF_VL   34048
#define OFF_KH   38400
#define OFF_WKH  42752
#define OFF_PH   47104      // p fp16 [16 q][64 s] = 512 floats, 128B rows swizzled
#define OFF_PL   47616
#define SMEM_FLOATS 48128   // 192512 bytes

__device__ float g_losses[Bn];

__device__ __forceinline__ float clip50(float x) {
    return fminf(fmaxf(x, -50.0f), 50.0f);
}
__device__ __forceinline__ ull dup2(float x) {
    ull r; asm("mov.b64 %0, {%1, %1};" : "=l"(r) : "f"(x)); return r;
}
__device__ __forceinline__ ull fma2(ull a, ull b, ull c) {
    ull d; asm("fma.rn.f32x2 %0, %1, %2, %3;" : "=l"(d) : "l"(a), "l"(b), "l"(c)); return d;
}
__device__ __forceinline__ float2 unpack2(ull p) {
    float2 f; asm("mov.b64 {%0, %1}, %2;" : "=f"(f.x), "=f"(f.y) : "l"(p)); return f;
}
__device__ __forceinline__ uint32_t smem_u32(const void* p) {
    uint32_t a;
    asm("{ .reg .u64 t; cvta.to.shared.u64 t, %1; cvt.u32.u64 %0, t; }" : "=r"(a) : "l"(p));
    return a;
}
__device__ __forceinline__ void split2h(float f0, float f1, uint32_t& hi, uint32_t& lo) {
    __half2 h = __floats2half2_rn(f0, f1);
    float2 hf = __half22float2(h);
    __half2 l = __floats2half2_rn(f0 - hf.x, f1 - hf.y);
    hi = *(uint32_t*)&h;
    lo = *(uint32_t*)&l;
}
__device__ __forceinline__ uint32_t cvt2h(float f0, float f1) {
    __half2 h = __floats2half2_rn(f0, f1);
    return *(uint32_t*)&h;
}
__device__ __forceinline__ uint32_t swz(uint32_t off) { return off ^ ((off >> 3) & 0x70); }

__device__ __forceinline__ void ldsm4(uint32_t& r0, uint32_t& r1, uint32_t& r2, uint32_t& r3, uint32_t a) {
    asm volatile("ldmatrix.sync.aligned.m8n8.x4.shared.b16 {%0,%1,%2,%3}, [%4];"
                 : "=r"(r0), "=r"(r1), "=r"(r2), "=r"(r3) : "r"(a));
}
__device__ __forceinline__ void ldsm4t(uint32_t& r0, uint32_t& r1, uint32_t& r2, uint32_t& r3, uint32_t a) {
    asm volatile("ldmatrix.sync.aligned.m8n8.x4.trans.shared.b16 {%0,%1,%2,%3}, [%4];"
                 : "=r"(r0), "=r"(r1), "=r"(r2), "=r"(r3) : "r"(a));
}
__device__ __forceinline__ void mma16816(float* d, const uint32_t* a, uint32_t b0, uint32_t b1) {
    asm volatile("mma.sync.aligned.m16n8k16.row.col.f32.f16.f16.f32 "
                 "{%0,%1,%2,%3}, {%4,%5,%6,%7}, {%8,%9}, {%0,%1,%2,%3};"
                 : "+f"(d[0]), "+f"(d[1]), "+f"(d[2]), "+f"(d[3])
                 : "r"(a[0]), "r"(a[1]), "r"(a[2]), "r"(a[3]), "r"(b0), "r"(b1));
}

__global__ void __launch_bounds__(NT, 1)
fml_kernel(const float* __restrict__ gq, const float* __restrict__ gk,
           const float* __restrict__ gv, const float* __restrict__ gkcg,
           const float* __restrict__ gvcg)
{
    extern __shared__ float sm[];
    char* smc = (char*)sm;
    const int b   = blockIdx.x;
    const int tid = threadIdx.x;
    const int wid = tid >> 5, lane = tid & 31;
    const float scale = 0.088388347648318447f;
    const uint32_t smb = smem_u32(sm);

    // ---- load qT [d][16] and cg tensors ----
    const float* qb = gq + (size_t)b * Qn * Dn;
    for (int i = tid; i < Qn * Dn; i += NT) {
        int qq = i >> 7, d = i & 127;
        sm[OFF_QT + d * 16 + qq] = qb[i];
    }
    const float* kcb = gkcg + (size_t)b * Mn * Dn;
    const float* vcb = gvcg + (size_t)b * Mn * Dn;
    for (int i = tid; i < Mn * Dn; i += NT) {
        int j = i >> 7, d = i & 127;
        sm[OFF_KCG + j * CGP + d] = kcb[i];
        sm[OFF_VCG + j * CGP + d] = vcb[i];
    }
    __syncthreads();

    // ---- cg scores / softmax / w_cg / out / kbar (exact SIMT) ----
    if (tid < Qn * Mn) {
        int qq = tid >> 3, j = tid & 7;
        float acc = 0.f;
        #pragma unroll 8
        for (int d = 0; d < Dn; ++d)
            acc = fmaf(sm[OFF_QT + d * 16 + qq], sm[OFF_KCG + j * CGP + d], acc);
        sm[OFF_PCG + qq * Mn + j] = acc * scale;
    }
    __syncthreads();
    if (tid < Qn) {
        float m = -1e30f;
        #pragma unroll
        for (int j = 0; j < Mn; ++j) m = fmaxf(m, sm[OFF_PCG + tid * Mn + j]);
        float ss = 0.f;
        #pragma unroll
        for (int j = 0; j < Mn; ++j) {
            float e = __expf(sm[OFF_PCG + tid * Mn + j] - m);
            sm[OFF_PCG + tid * Mn + j] = e; ss += e;
        }
        float inv = 1.f / ss;
        #pragma unroll
        for (int j = 0; j < Mn; ++j) sm[OFF_PCG + tid * Mn + j] *= inv;
    }
    __syncthreads();
    if (tid < Mn) {
        float a = 0.f;
        #pragma unroll
        for (int qq = 0; qq < Qn; ++qq) a += sm[OFF_PCG + qq * Mn + tid];
        sm[OFF_WCG + tid] = a;
    }
    if (tid < 256) {
        int qq = tid >> 4, dblk = tid & 15;
        ull o2[4], kb2[4];
        #pragma unroll
        for (int i = 0; i < 4; ++i) { o2[i] = 0ull; kb2[i] = 0ull; }
        #pragma unroll
        for (int j = 0; j < Mn; ++j) {
            ull pc2 = dup2(sm[OFF_PCG + qq * Mn + j]);
            ulonglong2 vA = *(const ulonglong2*)&sm[OFF_VCG + j * CGP + dblk * 8];
            ulonglong2 vB = *(const ulonglong2*)&sm[OFF_VCG + j * CGP + dblk * 8 + 4];
            ulonglong2 kA = *(const ulonglong2*)&sm[OFF_KCG + j * CGP + dblk * 8];
            ulonglong2 kB = *(const ulonglong2*)&sm[OFF_KCG + j * CGP + dblk * 8 + 4];
            o2[0]  = fma2(pc2, vA.x, o2[0]);  o2[1]  = fma2(pc2, vA.y, o2[1]);
            o2[2]  = fma2(pc2, vB.x, o2[2]);  o2[3]  = fma2(pc2, vB.y, o2[3]);
            kb2[0] = fma2(pc2, kA.x, kb2[0]); kb2[1] = fma2(pc2, kA.y, kb2[1]);
            kb2[2] = fma2(pc2, kB.x, kb2[2]); kb2[3] = fma2(pc2, kB.y, kb2[3]);
        }
        *(ulonglong2*)&sm[OFF_OCG  + qq * Dn + dblk * 8]     = make_ulonglong2(o2[0], o2[1]);
        *(ulonglong2*)&sm[OFF_OCG  + qq * Dn + dblk * 8 + 4] = make_ulonglong2(o2[2], o2[3]);
        *(ulonglong2*)&sm[OFF_KBCG + qq * Dn + dblk * 8]     = make_ulonglong2(kb2[0], kb2[1]);
        *(ulonglong2*)&sm[OFF_KBCG + qq * Dn + dblk * 8 + 4] = make_ulonglong2(kb2[2], kb2[3]);
    }

    // ---- dense scores (fp32 SIMT, exact): 8 q-groups x 64 s ----
    const float* kbase = gk + (size_t)b * Sn * Dn;
    const float* vbase = gv + (size_t)b * Sn * Dn;
    const int qg = tid >> 6;
    const int sl = tid & 63;
    for (int t = 0; t < NCHUNK; ++t) {
        __syncthreads();
        const float4* kg4 = (const float4*)(kbase + (size_t)t * TILE * Dn);
        #pragma unroll
        for (int it = 0; it < 4; ++it) {
            int fidx = tid + it * NT;
            int row = fidx >> 5, c4 = fidx & 31;
            float4 val = kg4[fidx];
            float* dst = &sm[OFF_K32 + row * 129 + c4 * 4];
            dst[0] = val.x; dst[1] = val.y; dst[2] = val.z; dst[3] = val.w;
        }
        __syncthreads();
        ull a01 = 0ull;
        #pragma unroll 8
        for (int d = 0; d < Dn; ++d) {
            ull kv2 = dup2(sm[OFF_K32 + sl * 129 + d]);
            ull q2 = *(const ull*)&sm[OFF_QT + d * 16 + qg * 2];
            a01 = fma2(q2, kv2, a01);
        }
        float2 f01 = unpack2(a01);
        int scol = t * TILE + sl;
        sm[OFF_P + (qg * 2 + 0) * PPITCH + scol] = f01.x * scale;
        sm[OFF_P + (qg * 2 + 1) * PPITCH + scol] = f01.y * scale;
    }
    __syncthreads();

    // ---- softmax: one row per warp ----
    {
        float* row = &sm[OFF_P + wid * PPITCH];
        float m = -1e30f;
        #pragma unroll
        for (int i = 0; i < 16; ++i) m = fmaxf(m, row[lane + 32 * i]);
        #pragma unroll
        for (int o = 16; o > 0; o >>= 1) m = fmaxf(m, __shfl_xor_sync(0xffffffffu, m, o));
        float ss = 0.f;
        float ev[16];
        #pragma unroll
        for (int i = 0; i < 16; ++i) { ev[i] = __expf(row[lane + 32 * i] - m); ss += ev[i]; }
        #pragma unroll
        for (int o = 16; o > 0; o >>= 1) ss += __shfl_xor_sync(0xffffffffu, ss, o);
        float inv = 1.f / ss;
        #pragma unroll
        for (int i = 0; i < 16; ++i) row[lane + 32 * i] = ev[i] * inv;
    }
    __syncthreads();
    {
        int s = tid;
        float a = 0.f;
        #pragma unroll
        for (int qq = 0; qq < Qn; ++qq) a += sm[OFF_P + qq * PPITCH + s];
        sm[OFF_W + s] = a;
    }

    // ---- main tensor-core pass: 16 warps, grid 8m x 2n, trans-ldsm ----
    const int grp = lane >> 3, li = lane & 7;
    // A-trans geometry (V, K fragments from [s][d]):
    const int asrow = (grp >> 1) * 8 + li;       // s within k-chunk
    const int ascol = (grp & 1) * 8;             // d offset within warp's 16
    // B-trans geometry (WK fragments from [s][d]):
    const int bsrow = (grp & 1) * 8 + li;
    const int bscol = (grp >> 1) * 8;
    // B non-trans geometry (p fragments from [q][s]):
    const int brow = (grp >> 1) * 8 + li;
    const int bkc  = (grp & 1) * 8;
    const int mw   = wid & 7;
    const int m0   = mw * 16;
    const int nj   = wid >> 3;

    float accJ[8][4];
    float accO[2][4];
    #pragma unroll
    for (int nt = 0; nt < 8; ++nt)
        #pragma unroll
        for (int e = 0; e < 4; ++e) accJ[nt][e] = 0.f;
    #pragma unroll
    for (int nt = 0; nt < 2; ++nt)
        #pragma unroll
        for (int e = 0; e < 4; ++e) accO[nt][e] = 0.f;

    for (int c = 0; c < NCHUNK; ++c) {
        const int s0 = c * TILE;
        __syncthreads();
        // ---- fused stage+convert: gmem -> fp16 [s][272B] tiles, in registers ----
        #pragma unroll
        for (int it = 0; it < 2; ++it) {
            int u = tid + it * NT;            // 0..1023 : 64 s x 16 dblk
            int s = u >> 4, dblk = u & 15;
            const float* ksrc = kbase + (size_t)(s0 + s) * Dn + dblk * 8;
            const float* vsrc = vbase + (size_t)(s0 + s) * Dn + dblk * 8;
            float4 k0 = *(const float4*)ksrc;
            float4 k1 = *(const float4*)(ksrc + 4);
            float4 v0 = *(const float4*)vsrc;
            float4 v1 = *(const float4*)(vsrc + 4);
            float ws = sm[OFF_W + s0 + s];
            uint32_t off = (uint32_t)(s * TPITCH + dblk * 16);
            *(uint4*)(smc + OFF_KH * 4 + off) =
                make_uint4(cvt2h(k0.x, k0.y), cvt2h(k0.z, k0.w),
                           cvt2h(k1.x, k1.y), cvt2h(k1.z, k1.w));
            *(uint4*)(smc + OFF_WKH * 4 + off) =
                make_uint4(cvt2h(k0.x * ws, k0.y * ws), cvt2h(k0.z * ws, k0.w * ws),
                           cvt2h(k1.x * ws, k1.y * ws), cvt2h(k1.z * ws, k1.w * ws));
            uint4 vh, vl;
            uint32_t h, l;
            split2h(v0.x, v0.y, h, l); vh.x = h; vl.x = l;
            split2h(v0.z, v0.w, h, l); vh.y = h; vl.y = l;
            split2h(v1.x, v1.y, h, l); vh.z = h; vl.z = l;
            split2h(v1.z, v1.w, h, l); vh.w = h; vl.w = l;
            *(uint4*)(smc + OFF_VH * 4 + off) = vh;
            *(uint4*)(smc + OFF_VL * 4 + off) = vl;
        }
        // p fp16 tiles: warp wid handles q = wid
        {
            int qq = wid;
            float p0 = sm[OFF_P + qq * PPITCH + s0 + 2 * lane];
            float p1 = sm[OFF_P + qq * PPITCH + s0 + 2 * lane + 1];
            uint32_t sw = swz((uint32_t)(qq * 128 + lane * 4));
            uint32_t hi, lo;
            split2h(p0, p1, hi, lo);
            *(uint32_t*)(smc + OFF_PH * 4 + sw) = hi;
            *(uint32_t*)(smc + OFF_PL * 4 + sw) = lo;
        }
        __syncthreads();

        // ---- fragments + MMAs ----
        #pragma unroll
        for (int k = 0; k < 4; ++k) {
            uint32_t vah[4], valo[4];
            uint32_t aoff = (uint32_t)((k * 16 + asrow) * TPITCH + (m0 + ascol) * 2);
            ldsm4t(vah[0], vah[1], vah[2], vah[3], smb + OFF_VH * 4 + aoff);
            ldsm4t(valo[0], valo[1], valo[2], valo[3], smb + OFF_VL * 4 + aoff);

            uint32_t ph[4], pl[4];
            uint32_t pa = swz((uint32_t)(brow * 128 + (k * 16 + bkc) * 2));
            ldsm4(ph[0], ph[1], ph[2], ph[3], smb + OFF_PH * 4 + pa);
            ldsm4(pl[0], pl[1], pl[2], pl[3], smb + OFF_PL * 4 + pa);

            if (nj == 0) {
                mma16816(accO[0], vah, ph[0], ph[1]);
                mma16816(accO[0], vah, pl[0], pl[1]);
                mma16816(accO[0], valo, ph[0], ph[1]);
                mma16816(accO[1], vah, ph[2], ph[3]);
                mma16816(accO[1], vah, pl[2], pl[3]);
                mma16816(accO[1], valo, ph[2], ph[3]);
            } else {
                uint32_t kah[4];
                ldsm4t(kah[0], kah[1], kah[2], kah[3], smb + OFF_KH * 4 + aoff);
                mma16816(accO[0], kah, ph[0], ph[1]);
                mma16816(accO[0], kah, pl[0], pl[1]);
                mma16816(accO[1], kah, ph[2], ph[3]);
                mma16816(accO[1], kah, pl[2], pl[3]);
            }
            #pragma unroll
            for (int np = 0; np < 4; ++np) {
                uint32_t bh[4];
                uint32_t ba = (uint32_t)((k * 16 + bsrow) * TPITCH +
                                         (nj * 64 + np * 16 + bscol) * 2);
                ldsm4t(bh[0], bh[1], bh[2], bh[3], smb + OFF_WKH * 4 + ba);
                mma16816(accJ[np * 2], vah, bh[0], bh[1]);
                mma16816(accJ[np * 2], valo, bh[0], bh[1]);
                mma16816(accJ[np * 2 + 1], vah, bh[2], bh[3]);
                mma16816(accJ[np * 2 + 1], valo, bh[2], bh[3]);
            }
        }
    }
    __syncthreads();

    // ---- write out^T (nj==0) / kbar^T (nj==1) to smem [q][d] ----
    {
        int r = lane >> 2, cc2 = (lane & 3) * 2;
        int base = (nj == 0) ? OFF_OUT : OFF_KBAR;
        #pragma unroll
        for (int nt = 0; nt < 2; ++nt) {
            int qq = nt * 8 + cc2;
            sm[base + qq * Dn + m0 + r]           = accO[nt][0];
            sm[base + (qq + 1) * Dn + m0 + r]     = accO[nt][1];
            sm[base + qq * Dn + m0 + r + 8]       = accO[nt][2];
            sm[base + (qq + 1) * Dn + m0 + r + 8] = accO[nt][3];
        }
    }
    __syncthreads();

    // ---- epilogue: J2 + cg jacobian + clip + cosine ----
    const int r = lane >> 2, cc2 = (lane & 3) * 2;
    float o0a[16], o1a[16], c0a[16], c1a[16], vc0[8], vc1[8];
    #pragma unroll
    for (int q = 0; q < 16; ++q) {
        o0a[q] = sm[OFF_OUT + q * Dn + m0 + r];
        o1a[q] = sm[OFF_OUT + q * Dn + m0 + r + 8];
        c0a[q] = sm[OFF_OCG + q * Dn + m0 + r];
        c1a[q] = sm[OFF_OCG + q * Dn + m0 + r + 8];
    }
    #pragma unroll
    for (int j = 0; j < 8; ++j) {
        float wc = sm[OFF_WCG + j];
        vc0[j] = wc * sm[OFF_VCG + j * CGP + m0 + r];
        vc1[j] = wc * sm[OFF_VCG + j * CGP + m0 + r + 8];
    }

    float dd = 0.f, ccv = 0.f, dc = 0.f;
    #pragma unroll
    for (int nt = 0; nt < 8; ++nt) {
        ull jd0, jd1, jc0, jc1;
        asm("mov.b64 %0, {%1, %2};" : "=l"(jd0) : "f"(accJ[nt][0]), "f"(accJ[nt][1]));
        asm("mov.b64 %0, {%1, %2};" : "=l"(jd1) : "f"(accJ[nt][2]), "f"(accJ[nt][3]));
        jc0 = 0ull; jc1 = 0ull;
        int colb = nj * 64 + nt * 8 + cc2;
        #pragma unroll
        for (int q = 0; q < 16; ++q) {
            ull kbp = *(const ull*)&sm[OFF_KBAR + q * Dn + colb];
            jd0 = fma2(dup2(-o0a[q]), kbp, jd0);
            jd1 = fma2(dup2(-o1a[q]), kbp, jd1);
        }
        #pragma unroll
        for (int j = 0; j < 8; ++j) {
            ull kcp = *(const ull*)&sm[OFF_KCG + j * CGP + colb];
            jc0 = fma2(dup2(vc0[j]), kcp, jc0);
            jc1 = fma2(dup2(vc1[j]), kcp, jc1);
        }
        #pragma unroll
        for (int q = 0; q < 16; ++q) {
            ull kbp = *(const ull*)&sm[OFF_KBCG + q * Dn + colb];
            jc0 = fma2(dup2(-c0a[q]), kbp, jc0);
            jc1 = fma2(dup2(-c1a[q]), kbp, jc1);
        }
        float2 d0 = unpack2(jd0), d1 = unpack2(jd1);
        float2 g0 = unpack2(jc0), g1 = unpack2(jc1);
        float jdv[4] = {d0.x, d0.y, d1.x, d1.y};
        float jcv[4] = {g0.x, g0.y, g1.x, g1.y};
        #pragma unroll
        for (int e = 0; e < 4; ++e) {
            float a = clip50(jdv[e] * scale);
            float g = clip50(jcv[e] * scale);
            dd  = fmaf(a, a, dd);
            ccv = fmaf(g, g, ccv);
            dc  = fmaf(a, g, dc);
        }
    }
    float cons = 0.f;
    #pragma unroll
    for (int i = 0; i < 4; ++i) {
        float dif = sm[OFF_OUT + tid * 4 + i] - sm[OFF_OCG + tid * 4 + i];
        cons = fmaf(dif, dif, cons);
    }

    #pragma unroll
    for (int o = 16; o > 0; o >>= 1) {
        dd   += __shfl_xor_sync(0xffffffffu, dd,   o);
        ccv  += __shfl_xor_sync(0xffffffffu, ccv,  o);
        dc   += __shfl_xor_sync(0xffffffffu, dc,   o);
        cons += __shfl_xor_sync(0xffffffffu, cons, o);
    }
    if (lane == 0) {
        sm[OFF_RED + wid * 4 + 0] = dd;
        sm[OFF_RED + wid * 4 + 1] = ccv;
        sm[OFF_RED + wid * 4 + 2] = dc;
        sm[OFF_RED + wid * 4 + 3] = cons;
    }
    __syncthreads();
    if (tid == 0) {
        float DD = 0.f, CC = 0.f, DC = 0.f, CO = 0.f;
        #pragma unroll
        for (int w8 = 0; w8 < 16; ++w8) {
            DD += sm[OFF_RED + w8 * 4 + 0];
            CC += sm[OFF_RED + w8 * 4 + 1];
            DC += sm[OFF_RED + w8 * 4 + 2];
            CO += sm[OFF_RED + w8 * 4 + 3];
        }
        float cosv = DC / (sqrtf(DD) * sqrtf(CC) + 1e-8f);
        g_losses[b] = (1.0f - cosv) + CO * (1.0f / (float)(Qn * Dn));
    }
}

__global__ void fml_reduce(float* out) {
    int lane = threadIdx.x;
    float a = 0.f;
    #pragma unroll
    for (int i = 0; i < 8; ++i) a += g_losses[lane * 8 + i];
    #pragma unroll
    for (int o = 16; o > 0; o >>= 1) a += __shfl_xor_sync(0xffffffffu, a, o);
    if (lane == 0) out[0] = a * (1.0f / (float)Bn);
}

extern "C" void kernel_launch(void* const* d_in, const int* in_sizes, int n_in,
                              void* d_out, int out_size)
{
    const float* q   = (const float*)d_in[0];
    const float* k   = (const float*)d_in[1];
    const float* v   = (const float*)d_in[2];
    const float* kcg = (const float*)d_in[3];
    const float* vcg = (const float*)d_in[4];

    cudaFuncSetAttribute(fml_kernel, cudaFuncAttributeMaxDynamicSharedMemorySize,
                         SMEM_FLOATS * (int)sizeof(float));
    fml_kernel<<<Bn, NT, SMEM_FLOATS * sizeof(float)>>>(q, k, v, kcg, vcg);
    fml_reduce<<<1, 32>>>((float*)d_out);
}

// round 12
// speedup vs baseline: 1.5041x; 1.2739x over previous
#include <cuda_runtime.h>
#include <cuda_fp16.h>
#include <cstdint>

#define Bn 256
#define Qn 16
#define Sn 512
#define Mn 8
#define Dn 128
#define NT 512
#define TILE 64
#define NCHUNK 8
#define PPITCH 520
#define CGP 132
#define TPITCH 272   // bytes per row in fp16 [s][d] / [q][d] tiles (256 data + 16 pad)

typedef unsigned long long ull;

// ---- shared memory layout (float offsets) ----
#define OFF_QT   0          // qT[128][16]
#define OFF_P    2048       // p[16][520]
#define OFF_W    10368      // w[512]
#define OFF_OUT  10880      // out [q][128]
#define OFF_KBAR 12928      // kbar [q][128]
#define OFF_OCG  14976      // cg out [q][128]
#define OFF_KBCG 17024      // cg kbar [q][128]
#define OFF_KCG  19072      // kcg[8][132]
#define OFF_VCG  20128      // vcg[8][132]
#define OFF_PCG  21184      // p_cg[16][8]
#define OFF_WCG  21312      // w_cg[8]
#define OFF_RED  21320      // 16 warps * 4 = 64
// fp16 [s][d] tiles: 64 rows x 272B = 4352 floats each
#define OFF_VH   29696
#define OFF_VL   34048
#define OFF_KH   38400
#define OFF_WKH  42752
#define OFF_PH   47104      // p fp16 [16 q][64 s] = 512 floats, 128B rows swizzled
#define OFF_PL   47616
#define SMEM_FLOATS 48128   // 192512 bytes
// scores-phase aliases (time-separated from phase B):
#define OFF_SKH  OFF_VH     // K fp16 hi [64 s][272B]
#define OFF_SKL  OFF_VL     // K fp16 lo
#define OFF_QH   OFF_WKH            // Q fp16 hi [16 q][272B] = 1088 floats
#define OFF_QL   (OFF_WKH + 1088)   // Q fp16 lo

__device__ float g_losses[Bn];

__device__ __forceinline__ float clip50(float x) {
    return fminf(fmaxf(x, -50.0f), 50.0f);
}
__device__ __forceinline__ ull dup2(float x) {
    ull r; asm("mov.b64 %0, {%1, %1};" : "=l"(r) : "f"(x)); return r;
}
__device__ __forceinline__ ull fma2(ull a, ull b, ull c) {
    ull d; asm("fma.rn.f32x2 %0, %1, %2, %3;" : "=l"(d) : "l"(a), "l"(b), "l"(c)); return d;
}
__device__ __forceinline__ float2 unpack2(ull p) {
    float2 f; asm("mov.b64 {%0, %1}, %2;" : "=f"(f.x), "=f"(f.y) : "l"(p)); return f;
}
__device__ __forceinline__ uint32_t smem_u32(const void* p) {
    uint32_t a;
    asm("{ .reg .u64 t; cvta.to.shared.u64 t, %1; cvt.u32.u64 %0, t; }" : "=r"(a) : "l"(p));
    return a;
}
__device__ __forceinline__ void split2h(float f0, float f1, uint32_t& hi, uint32_t& lo) {
    __half2 h = __floats2half2_rn(f0, f1);
    float2 hf = __half22float2(h);
    __half2 l = __floats2half2_rn(f0 - hf.x, f1 - hf.y);
    hi = *(uint32_t*)&h;
    lo = *(uint32_t*)&l;
}
__device__ __forceinline__ uint32_t cvt2h(float f0, float f1) {
    __half2 h = __floats2half2_rn(f0, f1);
    return *(uint32_t*)&h;
}
__device__ __forceinline__ uint32_t swz(uint32_t off) { return off ^ ((off >> 3) & 0x70); }

__device__ __forceinline__ void ldsm4(uint32_t& r0, uint32_t& r1, uint32_t& r2, uint32_t& r3, uint32_t a) {
    asm volatile("ldmatrix.sync.aligned.m8n8.x4.shared.b16 {%0,%1,%2,%3}, [%4];"
                 : "=r"(r0), "=r"(r1), "=r"(r2), "=r"(r3) : "r"(a));
}
__device__ __forceinline__ void ldsm4t(uint32_t& r0, uint32_t& r1, uint32_t& r2, uint32_t& r3, uint32_t a) {
    asm volatile("ldmatrix.sync.aligned.m8n8.x4.trans.shared.b16 {%0,%1,%2,%3}, [%4];"
                 : "=r"(r0), "=r"(r1), "=r"(r2), "=r"(r3) : "r"(a));
}
__device__ __forceinline__ void mma16816(float* d, const uint32_t* a, uint32_t b0, uint32_t b1) {
    asm volatile("mma.sync.aligned.m16n8k16.row.col.f32.f16.f16.f32 "
                 "{%0,%1,%2,%3}, {%4,%5,%6,%7}, {%8,%9}, {%0,%1,%2,%3};"
                 : "+f"(d[0]), "+f"(d[1]), "+f"(d[2]), "+f"(d[3])
                 : "r"(a[0]), "r"(a[1]), "r"(a[2]), "r"(a[3]), "r"(b0), "r"(b1));
}

__global__ void __launch_bounds__(NT, 1)
fml_kernel(const float* __restrict__ gq, const float* __restrict__ gk,
           const float* __restrict__ gv, const float* __restrict__ gkcg,
           const float* __restrict__ gvcg)
{
    extern __shared__ float sm[];
    char* smc = (char*)sm;
    const int b   = blockIdx.x;
    const int tid = threadIdx.x;
    const int wid = tid >> 5, lane = tid & 31;
    const float scale = 0.088388347648318447f;
    const uint32_t smb = smem_u32(sm);

    // ldmatrix lane geometry (verified R6/R11)
    const int grp = lane >> 3, li = lane & 7;
    const int arow = (grp & 1) * 8 + li;         // non-trans A rows
    const int akc  = (grp >> 1) * 8;             // non-trans A k-offset
    const int asrow = (grp >> 1) * 8 + li;       // trans A
    const int ascol = (grp & 1) * 8;
    const int bsrow = (grp & 1) * 8 + li;        // trans B
    const int bscol = (grp >> 1) * 8;
    const int brow = (grp >> 1) * 8 + li;        // non-trans B rows
    const int bkc  = (grp & 1) * 8;

    // ---- load qT [d][16], stage Q fp16 hi/lo [q][272B], load cg tensors ----
    const float* qb = gq + (size_t)b * Qn * Dn;
    for (int i = tid; i < Qn * Dn; i += NT) {
        int qq = i >> 7, d = i & 127;
        sm[OFF_QT + d * 16 + qq] = qb[i];
    }
    if (tid < 256) {
        int q = tid >> 4, dblk = tid & 15;
        const float* src = qb + q * Dn + dblk * 8;
        float4 f0 = *(const float4*)src;
        float4 f1 = *(const float4*)(src + 4);
        uint4 qh, ql;
        uint32_t h, l;
        split2h(f0.x, f0.y, h, l); qh.x = h; ql.x = l;
        split2h(f0.z, f0.w, h, l); qh.y = h; ql.y = l;
        split2h(f1.x, f1.y, h, l); qh.z = h; ql.z = l;
        split2h(f1.z, f1.w, h, l); qh.w = h; ql.w = l;
        uint32_t off = (uint32_t)(q * TPITCH + dblk * 16);
        *(uint4*)(smc + OFF_QH * 4 + off) = qh;
        *(uint4*)(smc + OFF_QL * 4 + off) = ql;
    }
    const float* kcb = gkcg + (size_t)b * Mn * Dn;
    const float* vcb = gvcg + (size_t)b * Mn * Dn;
    for (int i = tid; i < Mn * Dn; i += NT) {
        int j = i >> 7, d = i & 127;
        sm[OFF_KCG + j * CGP + d] = kcb[i];
        sm[OFF_VCG + j * CGP + d] = vcb[i];
    }
    __syncthreads();

    // ---- cg scores / softmax / w_cg / out / kbar (exact SIMT) ----
    if (tid < Qn * Mn) {
        int qq = tid >> 3, j = tid & 7;
        float acc = 0.f;
        #pragma unroll 8
        for (int d = 0; d < Dn; ++d)
            acc = fmaf(sm[OFF_QT + d * 16 + qq], sm[OFF_KCG + j * CGP + d], acc);
        sm[OFF_PCG + qq * Mn + j] = acc * scale;
    }
    __syncthreads();
    if (tid < Qn) {
        float m = -1e30f;
        #pragma unroll
        for (int j = 0; j < Mn; ++j) m = fmaxf(m, sm[OFF_PCG + tid * Mn + j]);
        float ss = 0.f;
        #pragma unroll
        for (int j = 0; j < Mn; ++j) {
            float e = __expf(sm[OFF_PCG + tid * Mn + j] - m);
            sm[OFF_PCG + tid * Mn + j] = e; ss += e;
        }
        float inv = 1.f / ss;
        #pragma unroll
        for (int j = 0; j < Mn; ++j) sm[OFF_PCG + tid * Mn + j] *= inv;
    }
    __syncthreads();
    if (tid < Mn) {
        float a = 0.f;
        #pragma unroll
        for (int qq = 0; qq < Qn; ++qq) a += sm[OFF_PCG + qq * Mn + tid];
        sm[OFF_WCG + tid] = a;
    }
    if (tid < 256) {
        int qq = tid >> 4, dblk = tid & 15;
        ull o2[4], kb2[4];
        #pragma unroll
        for (int i = 0; i < 4; ++i) { o2[i] = 0ull; kb2[i] = 0ull; }
        #pragma unroll
        for (int j = 0; j < Mn; ++j) {
            ull pc2 = dup2(sm[OFF_PCG + qq * Mn + j]);
            ulonglong2 vA = *(const ulonglong2*)&sm[OFF_VCG + j * CGP + dblk * 8];
            ulonglong2 vB = *(const ulonglong2*)&sm[OFF_VCG + j * CGP + dblk * 8 + 4];
            ulonglong2 kA = *(const ulonglong2*)&sm[OFF_KCG + j * CGP + dblk * 8];
            ulonglong2 kB = *(const ulonglong2*)&sm[OFF_KCG + j * CGP + dblk * 8 + 4];
            o2[0]  = fma2(pc2, vA.x, o2[0]);  o2[1]  = fma2(pc2, vA.y, o2[1]);
            o2[2]  = fma2(pc2, vB.x, o2[2]);  o2[3]  = fma2(pc2, vB.y, o2[3]);
            kb2[0] = fma2(pc2, kA.x, kb2[0]); kb2[1] = fma2(pc2, kA.y, kb2[1]);
            kb2[2] = fma2(pc2, kB.x, kb2[2]); kb2[3] = fma2(pc2, kB.y, kb2[3]);
        }
        *(ulonglong2*)&sm[OFF_OCG  + qq * Dn + dblk * 8]     = make_ulonglong2(o2[0], o2[1]);
        *(ulonglong2*)&sm[OFF_OCG  + qq * Dn + dblk * 8 + 4] = make_ulonglong2(o2[2], o2[3]);
        *(ulonglong2*)&sm[OFF_KBCG + qq * Dn + dblk * 8]     = make_ulonglong2(kb2[0], kb2[1]);
        *(ulonglong2*)&sm[OFF_KBCG + qq * Dn + dblk * 8 + 4] = make_ulonglong2(kb2[2], kb2[3]);
    }

    // ---- dense scores via HMMA (3-combo split precision) ----
    const float* kbase = gk + (size_t)b * Sn * Dn;
    const float* vbase = gv + (size_t)b * Sn * Dn;
    const int r  = lane >> 2;
    const int cq = (lane & 3) * 2;
    for (int t = 0; t < NCHUNK; ++t) {
        __syncthreads();
        // fused stage: gmem K -> fp16 [s][272B] hi/lo
        #pragma unroll
        for (int it = 0; it < 2; ++it) {
            int u = tid + it * NT;
            int s = u >> 4, dblk = u & 15;
            const float* ksrc = kbase + (size_t)(t * TILE + s) * Dn + dblk * 8;
            float4 k0 = *(const float4*)ksrc;
            float4 k1 = *(const float4*)(ksrc + 4);
            uint4 kh, kl;
            uint32_t h, l;
            split2h(k0.x, k0.y, h, l); kh.x = h; kl.x = l;
            split2h(k0.z, k0.w, h, l); kh.y = h; kl.y = l;
            split2h(k1.x, k1.y, h, l); kh.z = h; kl.z = l;
            split2h(k1.z, k1.w, h, l); kh.w = h; kl.w = l;
            uint32_t off = (uint32_t)(s * TPITCH + dblk * 16);
            *(uint4*)(smc + OFF_SKH * 4 + off) = kh;
            *(uint4*)(smc + OFF_SKL * 4 + off) = kl;
        }
        __syncthreads();
        if (wid < 8) {
            int mw = wid & 3;       // s-tile: 16 rows at mw*16
            int qj = wid >> 2;      // q-half: 8 q at qj*8
            float accS[4] = {0.f, 0.f, 0.f, 0.f};
            #pragma unroll
            for (int k = 0; k < 8; ++k) {
                uint32_t ah[4], al[4], qh[4], qlr[4];
                uint32_t aoff = (uint32_t)((mw * 16 + arow) * TPITCH + (k * 16 + akc) * 2);
                ldsm4(ah[0], ah[1], ah[2], ah[3], smb + OFF_SKH * 4 + aoff);
                ldsm4(al[0], al[1], al[2], al[3], smb + OFF_SKL * 4 + aoff);
                uint32_t boff = (uint32_t)(brow * TPITCH + (k * 16 + bkc) * 2);
                ldsm4(qh[0], qh[1], qh[2], qh[3], smb + OFF_QH * 4 + boff);
                ldsm4(qlr[0], qlr[1], qlr[2], qlr[3], smb + OFF_QL * 4 + boff);
                int bs = qj * 2;
                mma16816(accS, ah, qh[bs], qh[bs + 1]);
                mma16816(accS, ah, qlr[bs], qlr[bs + 1]);
                mma16816(accS, al, qh[bs], qh[bs + 1]);
            }
            int sb = t * TILE + mw * 16;
            int q0 = qj * 8 + cq;
            sm[OFF_P + q0 * PPITCH + sb + r]           = accS[0] * scale;
            sm[OFF_P + (q0 + 1) * PPITCH + sb + r]     = accS[1] * scale;
            sm[OFF_P + q0 * PPITCH + sb + r + 8]       = accS[2] * scale;
            sm[OFF_P + (q0 + 1) * PPITCH + sb + r + 8] = accS[3] * scale;
        }
    }
    __syncthreads();

    // ---- softmax: one row per warp ----
    {
        float* row = &sm[OFF_P + wid * PPITCH];
        float m = -1e30f;
        #pragma unroll
        for (int i = 0; i < 16; ++i) m = fmaxf(m, row[lane + 32 * i]);
        #pragma unroll
        for (int o = 16; o > 0; o >>= 1) m = fmaxf(m, __shfl_xor_sync(0xffffffffu, m, o));
        float ss = 0.f;
        float ev[16];
        #pragma unroll
        for (int i = 0; i < 16; ++i) { ev[i] = __expf(row[lane + 32 * i] - m); ss += ev[i]; }
        #pragma unroll
        for (int o = 16; o > 0; o >>= 1) ss += __shfl_xor_sync(0xffffffffu, ss, o);
        float inv = 1.f / ss;
        #pragma unroll
        for (int i = 0; i < 16; ++i) row[lane + 32 * i] = ev[i] * inv;
    }
    __syncthreads();
    {
        int s = tid;
        float a = 0.f;
        #pragma unroll
        for (int qq = 0; qq < Qn; ++qq) a += sm[OFF_P + qq * PPITCH + s];
        sm[OFF_W + s] = a;
    }

    // ---- main tensor-core pass: 16 warps, grid 8m x 2n, trans-ldsm (R11) ----
    const int mw   = wid & 7;
    const int m0   = mw * 16;
    const int nj   = wid >> 3;

    float accJ[8][4];
    float accO[2][4];
    #pragma unroll
    for (int nt = 0; nt < 8; ++nt)
        #pragma unroll
        for (int e = 0; e < 4; ++e) accJ[nt][e] = 0.f;
    #pragma unroll
    for (int nt = 0; nt < 2; ++nt)
        #pragma unroll
        for (int e = 0; e < 4; ++e) accO[nt][e] = 0.f;

    for (int c = 0; c < NCHUNK; ++c) {
        const int s0 = c * TILE;
        __syncthreads();
        #pragma unroll
        for (int it = 0; it < 2; ++it) {
            int u = tid + it * NT;
            int s = u >> 4, dblk = u & 15;
            const float* ksrc = kbase + (size_t)(s0 + s) * Dn + dblk * 8;
            const float* vsrc = vbase + (size_t)(s0 + s) * Dn + dblk * 8;
            float4 k0 = *(const float4*)ksrc;
            float4 k1 = *(const float4*)(ksrc + 4);
            float4 v0 = *(const float4*)vsrc;
            float4 v1 = *(const float4*)(vsrc + 4);
            float ws = sm[OFF_W + s0 + s];
            uint32_t off = (uint32_t)(s * TPITCH + dblk * 16);
            *(uint4*)(smc + OFF_KH * 4 + off) =
                make_uint4(cvt2h(k0.x, k0.y), cvt2h(k0.z, k0.w),
                           cvt2h(k1.x, k1.y), cvt2h(k1.z, k1.w));
            *(uint4*)(smc + OFF_WKH * 4 + off) =
                make_uint4(cvt2h(k0.x * ws, k0.y * ws), cvt2h(k0.z * ws, k0.w * ws),
                           cvt2h(k1.x * ws, k1.y * ws), cvt2h(k1.z * ws, k1.w * ws));
            uint4 vh, vl;
            uint32_t h, l;
            split2h(v0.x, v0.y, h, l); vh.x = h; vl.x = l;
            split2h(v0.z, v0.w, h, l); vh.y = h; vl.y = l;
            split2h(v1.x, v1.y, h, l); vh.z = h; vl.z = l;
            split2h(v1.z, v1.w, h, l); vh.w = h; vl.w = l;
            *(uint4*)(smc + OFF_VH * 4 + off) = vh;
            *(uint4*)(smc + OFF_VL * 4 + off) = vl;
        }
        {
            int qq = wid;
            float p0 = sm[OFF_P + qq * PPITCH + s0 + 2 * lane];
            float p1 = sm[OFF_P + qq * PPITCH + s0 + 2 * lane + 1];
            uint32_t sw = swz((uint32_t)(qq * 128 + lane * 4));
            uint32_t hi, lo;
            split2h(p0, p1, hi, lo);
            *(uint32_t*)(smc + OFF_PH * 4 + sw) = hi;
            *(uint32_t*)(smc + OFF_PL * 4 + sw) = lo;
        }
        __syncthreads();

        #pragma unroll
        for (int k = 0; k < 4; ++k) {
            uint32_t vah[4], valo[4];
            uint32_t aoff = (uint32_t)((k * 16 + asrow) * TPITCH + (m0 + ascol) * 2);
            ldsm4t(vah[0], vah[1], vah[2], vah[3], smb + OFF_VH * 4 + aoff);
            ldsm4t(valo[0], valo[1], valo[2], valo[3], smb + OFF_VL * 4 + aoff);

            uint32_t ph[4], pl[4];
            uint32_t pa = swz((uint32_t)(brow * 128 + (k * 16 + bkc) * 2));
            ldsm4(ph[0], ph[1], ph[2], ph[3], smb + OFF_PH * 4 + pa);
            ldsm4(pl[0], pl[1], pl[2], pl[3], smb + OFF_PL * 4 + pa);

            if (nj == 0) {
                mma16816(accO[0], vah, ph[0], ph[1]);
                mma16816(accO[0], vah, pl[0], pl[1]);
                mma16816(accO[0], valo, ph[0], ph[1]);
                mma16816(accO[1], vah, ph[2], ph[3]);
                mma16816(accO[1], vah, pl[2], pl[3]);
                mma16816(accO[1], valo, ph[2], ph[3]);
            } else {
                uint32_t kah[4];
                ldsm4t(kah[0], kah[1], kah[2], kah[3], smb + OFF_KH * 4 + aoff);
                mma16816(accO[0], kah, ph[0], ph[1]);
                mma16816(accO[0], kah, pl[0], pl[1]);
                mma16816(accO[1], kah, ph[2], ph[3]);
                mma16816(accO[1], kah, pl[2], pl[3]);
            }
            #pragma unroll
            for (int np = 0; np < 4; ++np) {
                uint32_t bh[4];
                uint32_t ba = (uint32_t)((k * 16 + bsrow) * TPITCH +
                                         (nj * 64 + np * 16 + bscol) * 2);
                ldsm4t(bh[0], bh[1], bh[2], bh[3], smb + OFF_WKH * 4 + ba);
                mma16816(accJ[np * 2], vah, bh[0], bh[1]);
                mma16816(accJ[np * 2], valo, bh[0], bh[1]);
                mma16816(accJ[np * 2 + 1], vah, bh[2], bh[3]);
                mma16816(accJ[np * 2 + 1], valo, bh[2], bh[3]);
            }
        }
    }
    __syncthreads();

    // ---- write out^T (nj==0) / kbar^T (nj==1) to smem [q][d] ----
    {
        int base = (nj == 0) ? OFF_OUT : OFF_KBAR;
        #pragma unroll
        for (int nt = 0; nt < 2; ++nt) {
            int qq = nt * 8 + cq;
            sm[base + qq * Dn + m0 + r]           = accO[nt][0];
            sm[base + (qq + 1) * Dn + m0 + r]     = accO[nt][1];
            sm[base + qq * Dn + m0 + r + 8]       = accO[nt][2];
            sm[base + (qq + 1) * Dn + m0 + r + 8] = accO[nt][3];
        }
    }
    __syncthreads();

    // ---- epilogue: J2 + cg jacobian + clip + cosine ----
    float o0a[16], o1a[16], c0a[16], c1a[16], vc0[8], vc1[8];
    #pragma unroll
    for (int q = 0; q < 16; ++q) {
        o0a[q] = sm[OFF_OUT + q * Dn + m0 + r];
        o1a[q] = sm[OFF_OUT + q * Dn + m0 + r + 8];
        c0a[q] = sm[OFF_OCG + q * Dn + m0 + r];
        c1a[q] = sm[OFF_OCG + q * Dn + m0 + r + 8];
    }
    #pragma unroll
    for (int j = 0; j < 8; ++j) {
        float wc = sm[OFF_WCG + j];
        vc0[j] = wc * sm[OFF_VCG + j * CGP + m0 + r];
        vc1[j] = wc * sm[OFF_VCG + j * CGP + m0 + r + 8];
    }

    float dd = 0.f, ccv = 0.f, dc = 0.f;
    #pragma unroll
    for (int nt = 0; nt < 8; ++nt) {
        ull jd0, jd1, jc0, jc1;
        asm("mov.b64 %0, {%1, %2};" : "=l"(jd0) : "f"(accJ[nt][0]), "f"(accJ[nt][1]));
        asm("mov.b64 %0, {%1, %2};" : "=l"(jd1) : "f"(accJ[nt][2]), "f"(accJ[nt][3]));
        jc0 = 0ull; jc1 = 0ull;
        int colb = nj * 64 + nt * 8 + cq;
        #pragma unroll
        for (int q = 0; q < 16; ++q) {
            ull kbp = *(const ull*)&sm[OFF_KBAR + q * Dn + colb];
            jd0 = fma2(dup2(-o0a[q]), kbp, jd0);
            jd1 = fma2(dup2(-o1a[q]), kbp, jd1);
        }
        #pragma unroll
        for (int j = 0; j < 8; ++j) {
            ull kcp = *(const ull*)&sm[OFF_KCG + j * CGP + colb];
            jc0 = fma2(dup2(vc0[j]), kcp, jc0);
            jc1 = fma2(dup2(vc1[j]), kcp, jc1);
        }
        #pragma unroll
        for (int q = 0; q < 16; ++q) {
            ull kbp = *(const ull*)&sm[OFF_KBCG + q * Dn + colb];
            jc0 = fma2(dup2(-c0a[q]), kbp, jc0);
            jc1 = fma2(dup2(-c1a[q]), kbp, jc1);
        }
        float2 d0 = unpack2(jd0), d1 = unpack2(jd1);
        float2 g0 = unpack2(jc0), g1 = unpack2(jc1);
        float jdv[4] = {d0.x, d0.y, d1.x, d1.y};
        float jcv[4] = {g0.x, g0.y, g1.x, g1.y};
        #pragma unroll
        for (int e = 0; e < 4; ++e) {
            float a = clip50(jdv[e] * scale);
            float g = clip50(jcv[e] * scale);
            dd  = fmaf(a, a, dd);
            ccv = fmaf(g, g, ccv);
            dc  = fmaf(a, g, dc);
        }
    }
    float cons = 0.f;
    #pragma unroll
    for (int i = 0; i < 4; ++i) {
        float dif = sm[OFF_OUT + tid * 4 + i] - sm[OFF_OCG + tid * 4 + i];
        cons = fmaf(dif, dif, cons);
    }

    #pragma unroll
    for (int o = 16; o > 0; o >>= 1) {
        dd   += __shfl_xor_sync(0xffffffffu, dd,   o);
        ccv  += __shfl_xor_sync(0xffffffffu, ccv,  o);
        dc   += __shfl_xor_sync(0xffffffffu, dc,   o);
        cons += __shfl_xor_sync(0xffffffffu, cons, o);
    }
    if (lane == 0) {
        sm[OFF_RED + wid * 4 + 0] = dd;
        sm[OFF_RED + wid * 4 + 1] = ccv;
        sm[OFF_RED + wid * 4 + 2] = dc;
        sm[OFF_RED + wid * 4 + 3] = cons;
    }
    __syncthreads();
    if (tid == 0) {
        float DD = 0.f, CC = 0.f, DC = 0.f, CO = 0.f;
        #pragma unroll
        for (int w8 = 0; w8 < 16; ++w8) {
            DD += sm[OFF_RED + w8 * 4 + 0];
            CC += sm[OFF_RED + w8 * 4 + 1];
            DC += sm[OFF_RED + w8 * 4 + 2];
            CO += sm[OFF_RED + w8 * 4 + 3];
        }
        float cosv = DC / (sqrtf(DD) * sqrtf(CC) + 1e-8f);
        g_losses[b] = (1.0f - cosv) + CO * (1.0f / (float)(Qn * Dn));
    }
}

__global__ void fml_reduce(float* out) {
    int lane = threadIdx.x;
    float a = 0.f;
    #pragma unroll
    for (int i = 0; i < 8; ++i) a += g_losses[lane * 8 + i];
    #pragma unroll
    for (int o = 16; o > 0; o >>= 1) a += __shfl_xor_sync(0xffffffffu, a, o);
    if (lane == 0) out[0] = a * (1.0f / (float)Bn);
}

extern "C" void kernel_launch(void* const* d_in, const int* in_sizes, int n_in,
                              void* d_out, int out_size)
{
    const float* q   = (const float*)d_in[0];
    const float* k   = (const float*)d_in[1];
    const float* v   = (const float*)d_in[2];
    const float* kcg = (const float*)d_in[3];
    const float* vcg = (const float*)d_in[4];

    cudaFuncSetAttribute(fml_kernel, cudaFuncAttributeMaxDynamicSharedMemorySize,
                         SMEM_FLOATS * (int)sizeof(float));
    fml_kernel<<<Bn, NT, SMEM_FLOATS * sizeof(float)>>>(q, k, v, kcg, vcg);
    fml_reduce<<<1, 32>>>((float*)d_out);
}

// round 13
// speedup vs baseline: 1.7030x; 1.1323x over previous
#include <cuda_runtime.h>
#include <cuda_fp16.h>
#include <cstdint>

#define Bn 256
#define Qn 16
#define Sn 512
#define Mn 8
#define Dn 128
#define NT 512
#define TILE 64
#define NCHUNK 8
#define PPITCH 520
#define CGP 132
#define TPITCH 272   // bytes per row in fp16 [s][d] / [q][d] tiles (256 data + 16 pad)

typedef unsigned long long ull;

// ---- shared memory layout (float offsets) ----
#define OFF_QT   0          // qT[128][16]
#define OFF_P    2048       // p[16][520]
#define OFF_W    10368      // w[512]
#define OFF_OUT  10880      // out [q][128]
#define OFF_KBAR 12928      // kbar [q][128]
#define OFF_OCG  14976      // cg out [q][128]
#define OFF_KBCG 17024      // cg kbar [q][128]
#define OFF_KCG  19072      // kcg[8][132]
#define OFF_VCG  20128      // vcg[8][132]
#define OFF_PCG  21184      // p_cg[16][8]
#define OFF_WCG  21312      // w_cg[8]
#define OFF_RED  21320      // 16 warps * 4 = 64
// fp16 [s][d] tiles: 64 rows x 272B = 4352 floats each
#define OFF_VH   29696
#define OFF_VL   34048
#define OFF_KH   38400
#define OFF_WKH  42752
#define OFF_PH   47104      // p fp16 [16 q][64 s] = 512 floats, 128B rows swizzled
#define OFF_PL   47616
#define SMEM_FLOATS 48128   // 192512 bytes
// scores-phase aliases (time-separated from phase B):
#define OFF_SKH  OFF_VH
#define OFF_SKL  OFF_VL
#define OFF_QH   OFF_WKH
#define OFF_QL   (OFF_WKH + 1088)

__device__ float g_losses[Bn];

__device__ __forceinline__ float clip50(float x) {
    return fminf(fmaxf(x, -50.0f), 50.0f);
}
__device__ __forceinline__ ull dup2(float x) {
    ull r; asm("mov.b64 %0, {%1, %1};" : "=l"(r) : "f"(x)); return r;
}
__device__ __forceinline__ ull fma2(ull a, ull b, ull c) {
    ull d; asm("fma.rn.f32x2 %0, %1, %2, %3;" : "=l"(d) : "l"(a), "l"(b), "l"(c)); return d;
}
__device__ __forceinline__ float2 unpack2(ull p) {
    float2 f; asm("mov.b64 {%0, %1}, %2;" : "=f"(f.x), "=f"(f.y) : "l"(p)); return f;
}
__device__ __forceinline__ uint32_t smem_u32(const void* p) {
    uint32_t a;
    asm("{ .reg .u64 t; cvta.to.shared.u64 t, %1; cvt.u32.u64 %0, t; }" : "=r"(a) : "l"(p));
    return a;
}
__device__ __forceinline__ void split2h(float f0, float f1, uint32_t& hi, uint32_t& lo) {
    __half2 h = __floats2half2_rn(f0, f1);
    float2 hf = __half22float2(h);
    __half2 l = __floats2half2_rn(f0 - hf.x, f1 - hf.y);
    hi = *(uint32_t*)&h;
    lo = *(uint32_t*)&l;
}
__device__ __forceinline__ uint32_t cvt2h(float f0, float f1) {
    __half2 h = __floats2half2_rn(f0, f1);
    return *(uint32_t*)&h;
}
__device__ __forceinline__ uint32_t swz(uint32_t off) { return off ^ ((off >> 3) & 0x70); }

__device__ __forceinline__ void ldsm4(uint32_t& r0, uint32_t& r1, uint32_t& r2, uint32_t& r3, uint32_t a) {
    asm volatile("ldmatrix.sync.aligned.m8n8.x4.shared.b16 {%0,%1,%2,%3}, [%4];"
                 : "=r"(r0), "=r"(r1), "=r"(r2), "=r"(r3) : "r"(a));
}
__device__ __forceinline__ void ldsm4t(uint32_t& r0, uint32_t& r1, uint32_t& r2, uint32_t& r3, uint32_t a) {
    asm volatile("ldmatrix.sync.aligned.m8n8.x4.trans.shared.b16 {%0,%1,%2,%3}, [%4];"
                 : "=r"(r0), "=r"(r1), "=r"(r2), "=r"(r3) : "r"(a));
}
__device__ __forceinline__ void mma16816(float* d, const uint32_t* a, uint32_t b0, uint32_t b1) {
    asm volatile("mma.sync.aligned.m16n8k16.row.col.f32.f16.f16.f32 "
                 "{%0,%1,%2,%3}, {%4,%5,%6,%7}, {%8,%9}, {%0,%1,%2,%3};"
                 : "+f"(d[0]), "+f"(d[1]), "+f"(d[2]), "+f"(d[3])
                 : "r"(a[0]), "r"(a[1]), "r"(a[2]), "r"(a[3]), "r"(b0), "r"(b1));
}

__global__ void __launch_bounds__(NT, 1)
fml_kernel(const float* __restrict__ gq, const float* __restrict__ gk,
           const float* __restrict__ gv, const float* __restrict__ gkcg,
           const float* __restrict__ gvcg)
{
    extern __shared__ float sm[];
    char* smc = (char*)sm;
    const int b   = blockIdx.x;
    const int tid = threadIdx.x;
    const int wid = tid >> 5, lane = tid & 31;
    const float scale = 0.088388347648318447f;
    const uint32_t smb = smem_u32(sm);

    // ldmatrix lane geometry
    const int grp = lane >> 3, li = lane & 7;
    const int arow = (grp & 1) * 8 + li;
    const int akc  = (grp >> 1) * 8;
    const int asrow = (grp >> 1) * 8 + li;
    const int ascol = (grp & 1) * 8;
    const int bsrow = (grp & 1) * 8 + li;
    const int bscol = (grp >> 1) * 8;
    const int brow = (grp >> 1) * 8 + li;
    const int bkc  = (grp & 1) * 8;

    // ---- load qT, stage Q fp16, load cg tensors ----
    const float* qb = gq + (size_t)b * Qn * Dn;
    for (int i = tid; i < Qn * Dn; i += NT) {
        int qq = i >> 7, d = i & 127;
        sm[OFF_QT + d * 16 + qq] = qb[i];
    }
    if (tid < 256) {
        int q = tid >> 4, dblk = tid & 15;
        const float* src = qb + q * Dn + dblk * 8;
        float4 f0 = *(const float4*)src;
        float4 f1 = *(const float4*)(src + 4);
        uint4 qh, ql;
        uint32_t h, l;
        split2h(f0.x, f0.y, h, l); qh.x = h; ql.x = l;
        split2h(f0.z, f0.w, h, l); qh.y = h; ql.y = l;
        split2h(f1.x, f1.y, h, l); qh.z = h; ql.z = l;
        split2h(f1.z, f1.w, h, l); qh.w = h; ql.w = l;
        uint32_t off = (uint32_t)(q * TPITCH + dblk * 16);
        *(uint4*)(smc + OFF_QH * 4 + off) = qh;
        *(uint4*)(smc + OFF_QL * 4 + off) = ql;
    }
    const float* kcb = gkcg + (size_t)b * Mn * Dn;
    const float* vcb = gvcg + (size_t)b * Mn * Dn;
    for (int i = tid; i < Mn * Dn; i += NT) {
        int j = i >> 7, d = i & 127;
        sm[OFF_KCG + j * CGP + d] = kcb[i];
        sm[OFF_VCG + j * CGP + d] = vcb[i];
    }
    __syncthreads();

    // ---- cg scores / softmax / w_cg / out / kbar (exact SIMT) ----
    if (tid < Qn * Mn) {
        int qq = tid >> 3, j = tid & 7;
        float acc = 0.f;
        #pragma unroll 8
        for (int d = 0; d < Dn; ++d)
            acc = fmaf(sm[OFF_QT + d * 16 + qq], sm[OFF_KCG + j * CGP + d], acc);
        sm[OFF_PCG + qq * Mn + j] = acc * scale;
    }
    __syncthreads();
    if (tid < Qn) {
        float m = -1e30f;
        #pragma unroll
        for (int j = 0; j < Mn; ++j) m = fmaxf(m, sm[OFF_PCG + tid * Mn + j]);
        float ss = 0.f;
        #pragma unroll
        for (int j = 0; j < Mn; ++j) {
            float e = __expf(sm[OFF_PCG + tid * Mn + j] - m);
            sm[OFF_PCG + tid * Mn + j] = e; ss += e;
        }
        float inv = 1.f / ss;
        #pragma unroll
        for (int j = 0; j < Mn; ++j) sm[OFF_PCG + tid * Mn + j] *= inv;
    }
    __syncthreads();
    if (tid < Mn) {
        float a = 0.f;
        #pragma unroll
        for (int qq = 0; qq < Qn; ++qq) a += sm[OFF_PCG + qq * Mn + tid];
        sm[OFF_WCG + tid] = a;
    }
    if (tid < 256) {
        int qq = tid >> 4, dblk = tid & 15;
        ull o2[4], kb2[4];
        #pragma unroll
        for (int i = 0; i < 4; ++i) { o2[i] = 0ull; kb2[i] = 0ull; }
        #pragma unroll
        for (int j = 0; j < Mn; ++j) {
            ull pc2 = dup2(sm[OFF_PCG + qq * Mn + j]);
            ulonglong2 vA = *(const ulonglong2*)&sm[OFF_VCG + j * CGP + dblk * 8];
            ulonglong2 vB = *(const ulonglong2*)&sm[OFF_VCG + j * CGP + dblk * 8 + 4];
            ulonglong2 kA = *(const ulonglong2*)&sm[OFF_KCG + j * CGP + dblk * 8];
            ulonglong2 kB = *(const ulonglong2*)&sm[OFF_KCG + j * CGP + dblk * 8 + 4];
            o2[0]  = fma2(pc2, vA.x, o2[0]);  o2[1]  = fma2(pc2, vA.y, o2[1]);
            o2[2]  = fma2(pc2, vB.x, o2[2]);  o2[3]  = fma2(pc2, vB.y, o2[3]);
            kb2[0] = fma2(pc2, kA.x, kb2[0]); kb2[1] = fma2(pc2, kA.y, kb2[1]);
            kb2[2] = fma2(pc2, kB.x, kb2[2]); kb2[3] = fma2(pc2, kB.y, kb2[3]);
        }
        *(ulonglong2*)&sm[OFF_OCG  + qq * Dn + dblk * 8]     = make_ulonglong2(o2[0], o2[1]);
        *(ulonglong2*)&sm[OFF_OCG  + qq * Dn + dblk * 8 + 4] = make_ulonglong2(o2[2], o2[3]);
        *(ulonglong2*)&sm[OFF_KBCG + qq * Dn + dblk * 8]     = make_ulonglong2(kb2[0], kb2[1]);
        *(ulonglong2*)&sm[OFF_KBCG + qq * Dn + dblk * 8 + 4] = make_ulonglong2(kb2[2], kb2[3]);
    }

    // ---- dense scores via HMMA (pipelined K prefetch) ----
    const float* kbase = gk + (size_t)b * Sn * Dn;
    const float* vbase = gv + (size_t)b * Sn * Dn;
    const int r  = lane >> 2;
    const int cq = (lane & 3) * 2;
    const int ps  = tid >> 4;        // staging row 0..31 (it=0) / +32 (it=1)
    const int pdb = tid & 15;        // staging dblk

    float4 sk[4];
    {   // prefetch t=0
        const float* k0p = kbase + (size_t)ps * Dn + pdb * 8;
        const float* k1p = kbase + (size_t)(ps + 32) * Dn + pdb * 8;
        sk[0] = *(const float4*)k0p; sk[1] = *(const float4*)(k0p + 4);
        sk[2] = *(const float4*)k1p; sk[3] = *(const float4*)(k1p + 4);
    }
    for (int t = 0; t < NCHUNK; ++t) {
        __syncthreads();
        // convert + store from registers
        #pragma unroll
        for (int it = 0; it < 2; ++it) {
            int s = ps + it * 32;
            float4 k0 = sk[it * 2], k1 = sk[it * 2 + 1];
            uint4 kh, kl;
            uint32_t h, l;
            split2h(k0.x, k0.y, h, l); kh.x = h; kl.x = l;
            split2h(k0.z, k0.w, h, l); kh.y = h; kl.y = l;
            split2h(k1.x, k1.y, h, l); kh.z = h; kl.z = l;
            split2h(k1.z, k1.w, h, l); kh.w = h; kl.w = l;
            uint32_t off = (uint32_t)(s * TPITCH + pdb * 16);
            *(uint4*)(smc + OFF_SKH * 4 + off) = kh;
            *(uint4*)(smc + OFF_SKL * 4 + off) = kl;
        }
        // prefetch t+1
        if (t + 1 < NCHUNK) {
            const float* k0p = kbase + (size_t)((t + 1) * TILE + ps) * Dn + pdb * 8;
            const float* k1p = kbase + (size_t)((t + 1) * TILE + ps + 32) * Dn + pdb * 8;
            sk[0] = *(const float4*)k0p; sk[1] = *(const float4*)(k0p + 4);
            sk[2] = *(const float4*)k1p; sk[3] = *(const float4*)(k1p + 4);
        }
        __syncthreads();
        if (wid < 8) {
            int mw = wid & 3;
            int qj = wid >> 2;
            float accS[4] = {0.f, 0.f, 0.f, 0.f};
            #pragma unroll
            for (int k = 0; k < 8; ++k) {
                uint32_t ah[4], al[4], qh[4], qlr[4];
                uint32_t aoff = (uint32_t)((mw * 16 + arow) * TPITCH + (k * 16 + akc) * 2);
                ldsm4(ah[0], ah[1], ah[2], ah[3], smb + OFF_SKH * 4 + aoff);
                ldsm4(al[0], al[1], al[2], al[3], smb + OFF_SKL * 4 + aoff);
                uint32_t boff = (uint32_t)(brow * TPITCH + (k * 16 + bkc) * 2);
                ldsm4(qh[0], qh[1], qh[2], qh[3], smb + OFF_QH * 4 + boff);
                ldsm4(qlr[0], qlr[1], qlr[2], qlr[3], smb + OFF_QL * 4 + boff);
                int bs = qj * 2;
                mma16816(accS, ah, qh[bs], qh[bs + 1]);
                mma16816(accS, ah, qlr[bs], qlr[bs + 1]);
                mma16816(accS, al, qh[bs], qh[bs + 1]);
            }
            int sb = t * TILE + mw * 16;
            int q0 = qj * 8 + cq;
            sm[OFF_P + q0 * PPITCH + sb + r]           = accS[0] * scale;
            sm[OFF_P + (q0 + 1) * PPITCH + sb + r]     = accS[1] * scale;
            sm[OFF_P + q0 * PPITCH + sb + r + 8]       = accS[2] * scale;
            sm[OFF_P + (q0 + 1) * PPITCH + sb + r + 8] = accS[3] * scale;
        }
    }
    __syncthreads();

    // ---- softmax: one row per warp ----
    {
        float* row = &sm[OFF_P + wid * PPITCH];
        float m = -1e30f;
        #pragma unroll
        for (int i = 0; i < 16; ++i) m = fmaxf(m, row[lane + 32 * i]);
        #pragma unroll
        for (int o = 16; o > 0; o >>= 1) m = fmaxf(m, __shfl_xor_sync(0xffffffffu, m, o));
        float ss = 0.f;
        float ev[16];
        #pragma unroll
        for (int i = 0; i < 16; ++i) { ev[i] = __expf(row[lane + 32 * i] - m); ss += ev[i]; }
        #pragma unroll
        for (int o = 16; o > 0; o >>= 1) ss += __shfl_xor_sync(0xffffffffu, ss, o);
        float inv = 1.f / ss;
        #pragma unroll
        for (int i = 0; i < 16; ++i) row[lane + 32 * i] = ev[i] * inv;
    }
    __syncthreads();
    {
        int s = tid;
        float a = 0.f;
        #pragma unroll
        for (int qq = 0; qq < Qn; ++qq) a += sm[OFF_P + qq * PPITCH + s];
        sm[OFF_W + s] = a;
    }

    // ---- main tensor-core pass (pipelined K/V prefetch) ----
    const int mw   = wid & 7;
    const int m0   = mw * 16;
    const int nj   = wid >> 3;

    float accJ[8][4];
    float accO[2][4];
    #pragma unroll
    for (int nt = 0; nt < 8; ++nt)
        #pragma unroll
        for (int e = 0; e < 4; ++e) accJ[nt][e] = 0.f;
    #pragma unroll
    for (int nt = 0; nt < 2; ++nt)
        #pragma unroll
        for (int e = 0; e < 4; ++e) accO[nt][e] = 0.f;

    float4 pk[4], pv[4];
    {   // prefetch c=0
        const float* k0p = kbase + (size_t)ps * Dn + pdb * 8;
        const float* k1p = kbase + (size_t)(ps + 32) * Dn + pdb * 8;
        const float* v0p = vbase + (size_t)ps * Dn + pdb * 8;
        const float* v1p = vbase + (size_t)(ps + 32) * Dn + pdb * 8;
        pk[0] = *(const float4*)k0p; pk[1] = *(const float4*)(k0p + 4);
        pk[2] = *(const float4*)k1p; pk[3] = *(const float4*)(k1p + 4);
        pv[0] = *(const float4*)v0p; pv[1] = *(const float4*)(v0p + 4);
        pv[2] = *(const float4*)v1p; pv[3] = *(const float4*)(v1p + 4);
    }

    for (int c = 0; c < NCHUNK; ++c) {
        const int s0 = c * TILE;
        __syncthreads();
        // convert + store from registers
        #pragma unroll
        for (int it = 0; it < 2; ++it) {
            int s = ps + it * 32;
            float4 k0 = pk[it * 2], k1 = pk[it * 2 + 1];
            float4 v0 = pv[it * 2], v1 = pv[it * 2 + 1];
            float ws = sm[OFF_W + s0 + s];
            uint32_t off = (uint32_t)(s * TPITCH + pdb * 16);
            *(uint4*)(smc + OFF_KH * 4 + off) =
                make_uint4(cvt2h(k0.x, k0.y), cvt2h(k0.z, k0.w),
                           cvt2h(k1.x, k1.y), cvt2h(k1.z, k1.w));
            *(uint4*)(smc + OFF_WKH * 4 + off) =
                make_uint4(cvt2h(k0.x * ws, k0.y * ws), cvt2h(k0.z * ws, k0.w * ws),
                           cvt2h(k1.x * ws, k1.y * ws), cvt2h(k1.z * ws, k1.w * ws));
            uint4 vh, vl;
            uint32_t h, l;
            split2h(v0.x, v0.y, h, l); vh.x = h; vl.x = l;
            split2h(v0.z, v0.w, h, l); vh.y = h; vl.y = l;
            split2h(v1.x, v1.y, h, l); vh.z = h; vl.z = l;
            split2h(v1.z, v1.w, h, l); vh.w = h; vl.w = l;
            *(uint4*)(smc + OFF_VH * 4 + off) = vh;
            *(uint4*)(smc + OFF_VL * 4 + off) = vl;
        }
        {
            int qq = wid;
            float p0 = sm[OFF_P + qq * PPITCH + s0 + 2 * lane];
            float p1 = sm[OFF_P + qq * PPITCH + s0 + 2 * lane + 1];
            uint32_t sw = swz((uint32_t)(qq * 128 + lane * 4));
            uint32_t hi, lo;
            split2h(p0, p1, hi, lo);
            *(uint32_t*)(smc + OFF_PH * 4 + sw) = hi;
            *(uint32_t*)(smc + OFF_PL * 4 + sw) = lo;
        }
        // prefetch c+1
        if (c + 1 < NCHUNK) {
            const float* k0p = kbase + (size_t)((c + 1) * TILE + ps) * Dn + pdb * 8;
            const float* k1p = kbase + (size_t)((c + 1) * TILE + ps + 32) * Dn + pdb * 8;
            const float* v0p = vbase + (size_t)((c + 1) * TILE + ps) * Dn + pdb * 8;
            const float* v1p = vbase + (size_t)((c + 1) * TILE + ps + 32) * Dn + pdb * 8;
            pk[0] = *(const float4*)k0p; pk[1] = *(const float4*)(k0p + 4);
            pk[2] = *(const float4*)k1p; pk[3] = *(const float4*)(k1p + 4);
            pv[0] = *(const float4*)v0p; pv[1] = *(const float4*)(v0p + 4);
            pv[2] = *(const float4*)v1p; pv[3] = *(const float4*)(v1p + 4);
        }
        __syncthreads();

        #pragma unroll
        for (int k = 0; k < 4; ++k) {
            uint32_t vah[4], valo[4];
            uint32_t aoff = (uint32_t)((k * 16 + asrow) * TPITCH + (m0 + ascol) * 2);
            ldsm4t(vah[0], vah[1], vah[2], vah[3], smb + OFF_VH * 4 + aoff);
            ldsm4t(valo[0], valo[1], valo[2], valo[3], smb + OFF_VL * 4 + aoff);

            uint32_t ph[4], pl[4];
            uint32_t pa = swz((uint32_t)(brow * 128 + (k * 16 + bkc) * 2));
            ldsm4(ph[0], ph[1], ph[2], ph[3], smb + OFF_PH * 4 + pa);
            ldsm4(pl[0], pl[1], pl[2], pl[3], smb + OFF_PL * 4 + pa);

            if (nj == 0) {
                mma16816(accO[0], vah, ph[0], ph[1]);
                mma16816(accO[0], vah, pl[0], pl[1]);
                mma16816(accO[0], valo, ph[0], ph[1]);
                mma16816(accO[1], vah, ph[2], ph[3]);
                mma16816(accO[1], vah, pl[2], pl[3]);
                mma16816(accO[1], valo, ph[2], ph[3]);
            } else {
                uint32_t kah[4];
                ldsm4t(kah[0], kah[1], kah[2], kah[3], smb + OFF_KH * 4 + aoff);
                mma16816(accO[0], kah, ph[0], ph[1]);
                mma16816(accO[0], kah, pl[0], pl[1]);
                mma16816(accO[1], kah, ph[2], ph[3]);
                mma16816(accO[1], kah, pl[2], pl[3]);
            }
            #pragma unroll
            for (int np = 0; np < 4; ++np) {
                uint32_t bh[4];
                uint32_t ba = (uint32_t)((k * 16 + bsrow) * TPITCH +
                                         (nj * 64 + np * 16 + bscol) * 2);
                ldsm4t(bh[0], bh[1], bh[2], bh[3], smb + OFF_WKH * 4 + ba);
                mma16816(accJ[np * 2], vah, bh[0], bh[1]);
                mma16816(accJ[np * 2], valo, bh[0], bh[1]);
                mma16816(accJ[np * 2 + 1], vah, bh[2], bh[3]);
                mma16816(accJ[np * 2 + 1], valo, bh[2], bh[3]);
            }
        }
    }
    __syncthreads();

    // ---- write out^T (nj==0) / kbar^T (nj==1) to smem [q][d] ----
    {
        int base = (nj == 0) ? OFF_OUT : OFF_KBAR;
        #pragma unroll
        for (int nt = 0; nt < 2; ++nt) {
            int qq = nt * 8 + cq;
            sm[base + qq * Dn + m0 + r]           = accO[nt][0];
            sm[base + (qq + 1) * Dn + m0 + r]     = accO[nt][1];
            sm[base + qq * Dn + m0 + r + 8]       = accO[nt][2];
            sm[base + (qq + 1) * Dn + m0 + r + 8] = accO[nt][3];
        }
    }
    __syncthreads();

    // ---- epilogue: J2 + cg jacobian + clip + cosine ----
    float o0a[16], o1a[16], c0a[16], c1a[16], vc0[8], vc1[8];
    #pragma unroll
    for (int q = 0; q < 16; ++q) {
        o0a[q] = sm[OFF_OUT + q * Dn + m0 + r];
        o1a[q] = sm[OFF_OUT + q * Dn + m0 + r + 8];
        c0a[q] = sm[OFF_OCG + q * Dn + m0 + r];
        c1a[q] = sm[OFF_OCG + q * Dn + m0 + r + 8];
    }
    #pragma unroll
    for (int j = 0; j < 8; ++j) {
        float wc = sm[OFF_WCG + j];
        vc0[j] = wc * sm[OFF_VCG + j * CGP + m0 + r];
        vc1[j] = wc * sm[OFF_VCG + j * CGP + m0 + r + 8];
    }

    float dd = 0.f, ccv = 0.f, dc = 0.f;
    #pragma unroll
    for (int nt = 0; nt < 8; ++nt) {
        ull jd0, jd1, jc0, jc1;
        asm("mov.b64 %0, {%1, %2};" : "=l"(jd0) : "f"(accJ[nt][0]), "f"(accJ[nt][1]));
        asm("mov.b64 %0, {%1, %2};" : "=l"(jd1) : "f"(accJ[nt][2]), "f"(accJ[nt][3]));
        jc0 = 0ull; jc1 = 0ull;
        int colb = nj * 64 + nt * 8 + cq;
        #pragma unroll
        for (int q = 0; q < 16; ++q) {
            ull kbp = *(const ull*)&sm[OFF_KBAR + q * Dn + colb];
            jd0 = fma2(dup2(-o0a[q]), kbp, jd0);
            jd1 = fma2(dup2(-o1a[q]), kbp, jd1);
        }
        #pragma unroll
        for (int j = 0; j < 8; ++j) {
            ull kcp = *(const ull*)&sm[OFF_KCG + j * CGP + colb];
            jc0 = fma2(dup2(vc0[j]), kcp, jc0);
            jc1 = fma2(dup2(vc1[j]), kcp, jc1);
        }
        #pragma unroll
        for (int q = 0; q < 16; ++q) {
            ull kbp = *(const ull*)&sm[OFF_KBCG + q * Dn + colb];
            jc0 = fma2(dup2(-c0a[q]), kbp, jc0);
            jc1 = fma2(dup2(-c1a[q]), kbp, jc1);
        }
        float2 d0 = unpack2(jd0), d1 = unpack2(jd1);
        float2 g0 = unpack2(jc0), g1 = unpack2(jc1);
        float jdv[4] = {d0.x, d0.y, d1.x, d1.y};
        float jcv[4] = {g0.x, g0.y, g1.x, g1.y};
        #pragma unroll
        for (int e = 0; e < 4; ++e) {
            float a = clip50(jdv[e] * scale);
            float g = clip50(jcv[e] * scale);
            dd  = fmaf(a, a, dd);
            ccv = fmaf(g, g, ccv);
            dc  = fmaf(a, g, dc);
        }
    }
    float cons = 0.f;
    #pragma unroll
    for (int i = 0; i < 4; ++i) {
        float dif = sm[OFF_OUT + tid * 4 + i] - sm[OFF_OCG + tid * 4 + i];
        cons = fmaf(dif, dif, cons);
    }

    #pragma unroll
    for (int o = 16; o > 0; o >>= 1) {
        dd   += __shfl_xor_sync(0xffffffffu, dd,   o);
        ccv  += __shfl_xor_sync(0xffffffffu, ccv,  o);
        dc   += __shfl_xor_sync(0xffffffffu, dc,   o);
        cons += __shfl_xor_sync(0xffffffffu, cons, o);
    }
    if (lane == 0) {
        sm[OFF_RED + wid * 4 + 0] = dd;
        sm[OFF_RED + wid * 4 + 1] = ccv;
        sm[OFF_RED + wid * 4 + 2] = dc;
        sm[OFF_RED + wid * 4 + 3] = cons;
    }
    __syncthreads();
    if (tid == 0) {
        float DD = 0.f, CC = 0.f, DC = 0.f, CO = 0.f;
        #pragma unroll
        for (int w8 = 0; w8 < 16; ++w8) {
            DD += sm[OFF_RED + w8 * 4 + 0];
            CC += sm[OFF_RED + w8 * 4 + 1];
            DC += sm[OFF_RED + w8 * 4 + 2];
            CO += sm[OFF_RED + w8 * 4 + 3];
        }
        float cosv = DC / (sqrtf(DD) * sqrtf(CC) + 1e-8f);
        g_losses[b] = (1.0f - cosv) + CO * (1.0f / (float)(Qn * Dn));
    }
}

__global__ void fml_reduce(float* out) {
    int lane = threadIdx.x;
    float a = 0.f;
    #pragma unroll
    for (int i = 0; i < 8; ++i) a += g_losses[lane * 8 + i];
    #pragma unroll
    for (int o = 16; o > 0; o >>= 1) a += __shfl_xor_sync(0xffffffffu, a, o);
    if (lane == 0) out[0] = a * (1.0f / (float)Bn);
}

extern "C" void kernel_launch(void* const* d_in, const int* in_sizes, int n_in,
                              void* d_out, int out_size)
{
    const float* q   = (const float*)d_in[0];
    const float* k   = (const float*)d_in[1];
    const float* v   = (const float*)d_in[2];
    const float* kcg = (const float*)d_in[3];
    const float* vcg = (const float*)d_in[4];

    cudaFuncSetAttribute(fml_kernel, cudaFuncAttributeMaxDynamicSharedMemorySize,
                         SMEM_FLOATS * (int)sizeof(float));
    fml_kernel<<<Bn, NT, SMEM_FLOATS * sizeof(float)>>>(q, k, v, kcg, vcg);
    fml_reduce<<<1, 32>>>((float*)d_out);
}